// round 1
// baseline (speedup 1.0000x reference)
#include <cuda_runtime.h>
#include <cuda_bf16.h>
#include <math.h>

// Problem constants
#define BATCH    2
#define LEN      1024
#define DMODEL   1024
#define DSTATE   16
#define DCONV    4
#define DINNER   2048           // EXPAND * DMODEL
#define DTRANK   64             // (DMODEL + 15)/16
#define XDBL_N   (DTRANK + 2*DSTATE)   // 96

// ---------------- scratch (device globals; no allocation allowed) ----------------
__device__ float g_xz[(size_t)BATCH * LEN * 2 * DINNER];   // 8.4M floats
__device__ float g_u [(size_t)BATCH * LEN * DINNER];       // post conv+silu
__device__ float g_xdbl[(size_t)BATCH * LEN * XDBL_N];
__device__ float g_delta[(size_t)BATCH * LEN * DINNER];
__device__ float g_y [(size_t)BATCH * LEN * DINNER];       // gated y before W_out
__device__ float g_A [(size_t)DINNER * DSTATE];            // A = -exp(A_log)

// ---------------- helpers ----------------
__device__ __forceinline__ float silu_f(float x) {
    return x / (1.0f + __expf(-x));
}
__device__ __forceinline__ float softplus_f(float x) {
    // numerically stable log1p(exp(x))
    return fmaxf(x, 0.0f) + log1pf(expf(-fabsf(x)));
}

// ---------------- A precompute ----------------
__global__ void neg_exp_kernel(const float* __restrict__ A_log, float* __restrict__ A, int n) {
    int i = blockIdx.x * blockDim.x + threadIdx.x;
    if (i < n) A[i] = -__expf(A_log[i]);
}

// ---------------- generic fp32 tiled GEMM ----------------
// C[M,N] = A[M,K](lda) @ B[K,N]   (+ optional bias + softplus)
#define GBM 64
#define GBN 64
#define GBK 16
#define GTM 4
#define GTN 4
// 256 threads per block

__global__ void gemm_f32(const float* __restrict__ A, int lda,
                         const float* __restrict__ B,
                         const float* __restrict__ bias,
                         float* __restrict__ C,
                         int M, int N, int K, int act)
{
    __shared__ float As[GBK][GBM + 4];
    __shared__ float Bs[GBK][GBN + 4];

    int tid  = threadIdx.x;
    int tcol = tid % (GBN / GTN);     // 0..15
    int trow = tid / (GBN / GTN);     // 0..15
    int row0 = blockIdx.y * GBM;
    int col0 = blockIdx.x * GBN;

    float acc[GTM][GTN];
#pragma unroll
    for (int i = 0; i < GTM; i++)
#pragma unroll
        for (int j = 0; j < GTN; j++) acc[i][j] = 0.0f;

    for (int k0 = 0; k0 < K; k0 += GBK) {
        // load A tile (BM x BK)
#pragma unroll
        for (int i = tid; i < GBM * GBK; i += 256) {
            int m  = i / GBK;
            int kk = i % GBK;
            int gr = row0 + m, gc = k0 + kk;
            As[kk][m] = (gr < M && gc < K) ? A[(size_t)gr * lda + gc] : 0.0f;
        }
        // load B tile (BK x BN)
#pragma unroll
        for (int i = tid; i < GBK * GBN; i += 256) {
            int kk = i / GBN;
            int n  = i % GBN;
            int gr = k0 + kk, gc = col0 + n;
            Bs[kk][n] = (gr < K && gc < N) ? B[(size_t)gr * N + gc] : 0.0f;
        }
        __syncthreads();

#pragma unroll
        for (int kk = 0; kk < GBK; kk++) {
            float a[GTM], b[GTN];
#pragma unroll
            for (int i = 0; i < GTM; i++) a[i] = As[kk][trow * GTM + i];
#pragma unroll
            for (int j = 0; j < GTN; j++) b[j] = Bs[kk][tcol * GTN + j];
#pragma unroll
            for (int i = 0; i < GTM; i++)
#pragma unroll
                for (int j = 0; j < GTN; j++)
                    acc[i][j] = fmaf(a[i], b[j], acc[i][j]);
        }
        __syncthreads();
    }

#pragma unroll
    for (int i = 0; i < GTM; i++) {
        int gr = row0 + trow * GTM + i;
        if (gr >= M) continue;
#pragma unroll
        for (int j = 0; j < GTN; j++) {
            int gc = col0 + tcol * GTN + j;
            if (gc >= N) continue;
            float v = acc[i][j];
            if (act == 1) v = softplus_f(v + bias[gc]);
            C[(size_t)gr * N + gc] = v;
        }
    }
}

// ---------------- causal depthwise conv (width 4) + bias + silu ----------------
__global__ void conv_silu_kernel(const float* __restrict__ xz,
                                 const float* __restrict__ conv_w,
                                 const float* __restrict__ conv_b,
                                 float* __restrict__ u_out)
{
    int idx = blockIdx.x * blockDim.x + threadIdx.x;
    int total = BATCH * LEN * DINNER;
    if (idx >= total) return;
    int d = idx % DINNER;
    int l = (idx / DINNER) % LEN;
    int b = idx / (DINNER * LEN);

    float w0 = conv_w[d * DCONV + 0];
    float w1 = conv_w[d * DCONV + 1];
    float w2 = conv_w[d * DCONV + 2];
    float w3 = conv_w[d * DCONV + 3];

    const float* base = xz + (size_t)b * LEN * 2 * DINNER + d;  // u-part column d
    float acc = conv_b[d];
    int ll;
    ll = l - 3; if (ll >= 0) acc = fmaf(base[(size_t)ll * 2 * DINNER], w0, acc);
    ll = l - 2; if (ll >= 0) acc = fmaf(base[(size_t)ll * 2 * DINNER], w1, acc);
    ll = l - 1; if (ll >= 0) acc = fmaf(base[(size_t)ll * 2 * DINNER], w2, acc);
    acc = fmaf(base[(size_t)l * 2 * DINNER], w3, acc);

    u_out[idx] = silu_f(acc);
}

// ---------------- selective scan, 8 threads per channel (2 states each) ----------
// Fuses: deltaA = exp(delta*A), h = dA*h + delta*u*B, y = h.C,
//        y = (y + u*D_skip) * silu(z)
__global__ void scan_kernel(const float* __restrict__ delta,
                            const float* __restrict__ u,
                            const float* __restrict__ xdbl,
                            const float* __restrict__ xz,
                            const float* __restrict__ A,
                            const float* __restrict__ D_skip,
                            float* __restrict__ y)
{
    int tid  = blockIdx.x * blockDim.x + threadIdx.x;
    int t    = tid & 7;                 // state-pair id within channel
    int chan = tid >> 3;                // 0 .. BATCH*DINNER-1
    if (chan >= BATCH * DINNER) return;
    int b = chan / DINNER;
    int d = chan % DINNER;
    int n0 = t * 2;

    float a0 = A[d * DSTATE + n0];
    float a1 = A[d * DSTATE + n0 + 1];
    float dskip = D_skip[d];

    const float* dptr = delta + (size_t)b * LEN * DINNER + d;
    const float* uptr = u     + (size_t)b * LEN * DINNER + d;
    const float* xd   = xdbl  + (size_t)b * LEN * XDBL_N;
    const float* zptr = xz    + (size_t)b * LEN * 2 * DINNER + DINNER + d;
    float*       yptr = y     + (size_t)b * LEN * DINNER + d;

    float h0 = 0.0f, h1 = 0.0f;

    for (int l = 0; l < LEN; l++) {
        float dl = dptr[(size_t)l * DINNER];
        float ul = uptr[(size_t)l * DINNER];
        const float* xr = xd + (size_t)l * XDBL_N;
        float Bn0 = xr[DTRANK + n0];
        float Bn1 = xr[DTRANK + n0 + 1];
        float Cn0 = xr[DTRANK + DSTATE + n0];
        float Cn1 = xr[DTRANK + DSTATE + n0 + 1];

        float du = dl * ul;
        h0 = fmaf(__expf(dl * a0), h0, du * Bn0);
        h1 = fmaf(__expf(dl * a1), h1, du * Bn1);

        float part = fmaf(h0, Cn0, h1 * Cn1);
        part += __shfl_xor_sync(0xffffffffu, part, 1);
        part += __shfl_xor_sync(0xffffffffu, part, 2);
        part += __shfl_xor_sync(0xffffffffu, part, 4);

        if (t == 0) {
            float z = zptr[(size_t)l * 2 * DINNER];
            yptr[(size_t)l * DINNER] = (part + ul * dskip) * silu_f(z);
        }
    }
}

// ---------------- launcher ----------------
extern "C" void kernel_launch(void* const* d_in, const int* in_sizes, int n_in,
                              void* d_out, int out_size)
{
    const float* x      = (const float*)d_in[0];   // (B, L, DMODEL)
    const float* W_in   = (const float*)d_in[1];   // (DMODEL, 2*DINNER)
    const float* conv_w = (const float*)d_in[2];   // (DINNER, DCONV)
    const float* conv_b = (const float*)d_in[3];   // (DINNER,)
    const float* W_x    = (const float*)d_in[4];   // (DINNER, 96)
    const float* W_dt   = (const float*)d_in[5];   // (DTRANK, DINNER)
    const float* b_dt   = (const float*)d_in[6];   // (DINNER,)
    const float* A_log  = (const float*)d_in[7];   // (DINNER, DSTATE)
    const float* D_skip = (const float*)d_in[8];   // (DINNER,)
    const float* W_out  = (const float*)d_in[9];   // (DINNER, DMODEL)
    float* out = (float*)d_out;

    float *xz, *u, *xdbl, *delta, *yg, *Aneg;
    cudaGetSymbolAddress((void**)&xz,    g_xz);
    cudaGetSymbolAddress((void**)&u,     g_u);
    cudaGetSymbolAddress((void**)&xdbl,  g_xdbl);
    cudaGetSymbolAddress((void**)&delta, g_delta);
    cudaGetSymbolAddress((void**)&yg,    g_y);
    cudaGetSymbolAddress((void**)&Aneg,  g_A);

    const int M = BATCH * LEN;   // 2048

    // A = -exp(A_log)
    {
        int n = DINNER * DSTATE;
        neg_exp_kernel<<<(n + 255) / 256, 256>>>(A_log, Aneg, n);
    }

    // 1) xz = x @ W_in   [2048 x 1024] @ [1024 x 4096]
    {
        dim3 grid((2 * DINNER + GBN - 1) / GBN, (M + GBM - 1) / GBM);
        gemm_f32<<<grid, 256>>>(x, DMODEL, W_in, nullptr, xz,
                                M, 2 * DINNER, DMODEL, 0);
    }

    // 2) conv + silu -> u
    {
        int total = BATCH * LEN * DINNER;
        conv_silu_kernel<<<(total + 255) / 256, 256>>>(xz, conv_w, conv_b, u);
    }

    // 3) x_dbl = u @ W_x   [2048 x 2048] @ [2048 x 96]
    {
        dim3 grid((XDBL_N + GBN - 1) / GBN, (M + GBM - 1) / GBM);
        gemm_f32<<<grid, 256>>>(u, DINNER, W_x, nullptr, xdbl,
                                M, XDBL_N, DINNER, 0);
    }

    // 4) delta = softplus(dt @ W_dt + b_dt)   dt is xdbl[..., :64] with row stride 96
    {
        dim3 grid((DINNER + GBN - 1) / GBN, (M + GBM - 1) / GBM);
        gemm_f32<<<grid, 256>>>(xdbl, XDBL_N, W_dt, b_dt, delta,
                                M, DINNER, DTRANK, 1);
    }

    // 5) selective scan + gating -> yg
    {
        int threads_total = BATCH * DINNER * 8;   // 32768
        scan_kernel<<<threads_total / 256, 256>>>(delta, u, xdbl, xz,
                                                  Aneg, D_skip, yg);
    }

    // 6) out = yg @ W_out   [2048 x 2048] @ [2048 x 1024]
    {
        dim3 grid((DMODEL + GBN - 1) / GBN, (M + GBM - 1) / GBM);
        gemm_f32<<<grid, 256>>>(yg, DINNER, W_out, nullptr, out,
                                M, DMODEL, DINNER, 0);
    }
}

// round 4
// speedup vs baseline: 1.8762x; 1.8762x over previous
#include <cuda_runtime.h>
#include <math.h>
#include <cstdint>

// ---------------- problem constants ----------------
#define BATCH   2
#define LEN     1024
#define DMODEL  1024
#define DSTATE  16
#define DCONV   4
#define DINNER  2048
#define DTRANK  64
#define XDBL_N  (DTRANK + 2*DSTATE)   // 96
#define MTOT    (BATCH*LEN)           // 2048

// ---------------- scratch (device globals) ----------------
__device__ __align__(256) float g_xz   [(size_t)MTOT * 2 * DINNER];
__device__ __align__(256) float g_u    [(size_t)MTOT * DINNER];
__device__ __align__(256) float g_xdbl [(size_t)MTOT * XDBL_N];
__device__ __align__(256) float g_delta[(size_t)MTOT * DINNER];
__device__ __align__(256) float g_y    [(size_t)MTOT * DINNER];
__device__ __align__(256) float g_Aneg [DINNER * DSTATE];

// ---------------- helpers ----------------
__device__ __forceinline__ float silu_f(float x)     { return x / (1.0f + __expf(-x)); }
__device__ __forceinline__ float softplus_f(float x) { return fmaxf(x, 0.0f) + log1pf(expf(-fabsf(x))); }

// round fp32 -> tf32 (rna), returned as the representable fp32 value
__device__ __forceinline__ float tf32r(float x) {
    uint32_t r;
    asm("cvt.rna.tf32.f32 %0, %1;" : "=r"(r) : "f"(x));
    return __uint_as_float(r);
}

__device__ __forceinline__ void mma_tf32(float c[4],
                                         uint32_t a0, uint32_t a1, uint32_t a2, uint32_t a3,
                                         uint32_t b0, uint32_t b1) {
    asm volatile(
        "mma.sync.aligned.m16n8k8.row.col.f32.tf32.tf32.f32 "
        "{%0,%1,%2,%3}, {%4,%5,%6,%7}, {%8,%9}, {%0,%1,%2,%3};"
        : "+f"(c[0]), "+f"(c[1]), "+f"(c[2]), "+f"(c[3])
        : "r"(a0), "r"(a1), "r"(a2), "r"(a3), "r"(b0), "r"(b1));
}

// ---------------- A precompute ----------------
__global__ void neg_exp_kernel(const float* __restrict__ A_log, float* __restrict__ A, int n) {
    int i = blockIdx.x * blockDim.x + threadIdx.x;
    if (i < n) A[i] = -__expf(A_log[i]);
}

// ================= tf32x3 tensor-core GEMM =================
// C[M,N] = A[M,K](lda) @ B[K,N](ldb)   (+ optional bias + softplus)
// Block tile 128x64, BK=16, 256 threads (8 warps as 4x2), warp tile 32x32.
// Smem layouts (floats):  A: [128][20]  (stride 20 -> conflict-free frag loads)
//                         B: [16][72]   (stride 72 -> conflict-free frag loads)
#define SA 20
#define SB 72
#define AH_OFF 0
#define AL_OFF 5120          // 2 bufs * 128*20
#define BH_OFF 10240
#define BL_OFF 12544         // BH + 2 bufs * 16*72
#define GEMM_SMEM_FLOATS 14848
#define GEMM_SMEM_BYTES  (GEMM_SMEM_FLOATS * 4)   // 59392

__global__ void __launch_bounds__(256, 2)
gemm_tf32(const float* __restrict__ A, int lda,
          const float* __restrict__ B, int ldb,
          const float* __restrict__ bias,
          float* __restrict__ C, int ldc,
          int N, int K, int act)
{
    extern __shared__ float sm[];
    int tid = threadIdx.x;
    int row0 = blockIdx.y * 128;
    int col0 = blockIdx.x * 64;

    // staging maps
    int ar  = tid >> 2;           // 0..63 (A row; also +64)
    int akq = (tid & 3) << 2;     // k offset 0,4,8,12
    int bk  = tid >> 4;           // 0..15  (B k row)
    int bnq = (tid & 15) << 2;    // n offset 0..60

    // compute maps
    int lane = tid & 31;
    int rin = lane >> 2;          // 0..7
    int cin = lane & 3;           // 0..3
    int wid = tid >> 5;
    int warp_m = (wid & 3) * 32;  // 0,32,64,96
    int warp_n = (wid >> 2) * 32; // 0,32

    const float* Aptr = A + (size_t)row0 * lda;

    float acc[2][4][4];
#pragma unroll
    for (int mt = 0; mt < 2; mt++)
#pragma unroll
        for (int nt = 0; nt < 4; nt++)
#pragma unroll
            for (int i = 0; i < 4; i++) acc[mt][nt][i] = 0.0f;

    int nk = K >> 4;
    float4 rA0, rA1, rB;

    // ---- prologue: load chunk 0 ----
    {
        rA0 = *(const float4*)(Aptr + (size_t)ar * lda + akq);
        rA1 = *(const float4*)(Aptr + (size_t)(ar + 64) * lda + akq);
        int bcol = col0 + bnq;
        rB = (bcol < N) ? *(const float4*)(B + (size_t)bk * ldb + bcol)
                        : make_float4(0.f, 0.f, 0.f, 0.f);
    }

    for (int kc = 0; kc < nk; kc++) {
        int buf = kc & 1;
        // store current staged regs (split hi/lo) into smem[buf]
        {
            float* ah = sm + AH_OFF + buf * 2560;
            float* al = sm + AL_OFF + buf * 2560;
            float* bh = sm + BH_OFF + buf * 1152;
            float* bl = sm + BL_OFF + buf * 1152;
            float4 h, l;
            h.x = tf32r(rA0.x); h.y = tf32r(rA0.y); h.z = tf32r(rA0.z); h.w = tf32r(rA0.w);
            l.x = tf32r(rA0.x - h.x); l.y = tf32r(rA0.y - h.y);
            l.z = tf32r(rA0.z - h.z); l.w = tf32r(rA0.w - h.w);
            *(float4*)(ah + ar * SA + akq) = h;
            *(float4*)(al + ar * SA + akq) = l;
            h.x = tf32r(rA1.x); h.y = tf32r(rA1.y); h.z = tf32r(rA1.z); h.w = tf32r(rA1.w);
            l.x = tf32r(rA1.x - h.x); l.y = tf32r(rA1.y - h.y);
            l.z = tf32r(rA1.z - h.z); l.w = tf32r(rA1.w - h.w);
            *(float4*)(ah + (ar + 64) * SA + akq) = h;
            *(float4*)(al + (ar + 64) * SA + akq) = l;
            h.x = tf32r(rB.x); h.y = tf32r(rB.y); h.z = tf32r(rB.z); h.w = tf32r(rB.w);
            l.x = tf32r(rB.x - h.x); l.y = tf32r(rB.y - h.y);
            l.z = tf32r(rB.z - h.z); l.w = tf32r(rB.w - h.w);
            *(float4*)(bh + bk * SB + bnq) = h;
            *(float4*)(bl + bk * SB + bnq) = l;
        }
        __syncthreads();

        // issue gmem loads for next chunk
        if (kc + 1 < nk) {
            int k0 = (kc + 1) << 4;
            rA0 = *(const float4*)(Aptr + (size_t)ar * lda + k0 + akq);
            rA1 = *(const float4*)(Aptr + (size_t)(ar + 64) * lda + k0 + akq);
            int bcol = col0 + bnq;
            rB = (bcol < N) ? *(const float4*)(B + (size_t)(k0 + bk) * ldb + bcol)
                            : make_float4(0.f, 0.f, 0.f, 0.f);
        }

        // compute on smem[buf]
        {
            const float* ah = sm + AH_OFF + buf * 2560;
            const float* al = sm + AL_OFF + buf * 2560;
            const float* bh = sm + BH_OFF + buf * 1152;
            const float* bl = sm + BL_OFF + buf * 1152;
#pragma unroll
            for (int ks = 0; ks < 2; ks++) {
                int k8 = ks * 8;
                uint32_t Ah[2][4], Al[2][4], Bh[4][2], Bl[4][2];
#pragma unroll
                for (int mt = 0; mt < 2; mt++) {
                    int mb = warp_m + mt * 16 + rin;
                    Ah[mt][0] = __float_as_uint(ah[mb * SA + k8 + cin]);
                    Ah[mt][1] = __float_as_uint(ah[(mb + 8) * SA + k8 + cin]);
                    Ah[mt][2] = __float_as_uint(ah[mb * SA + k8 + cin + 4]);
                    Ah[mt][3] = __float_as_uint(ah[(mb + 8) * SA + k8 + cin + 4]);
                    Al[mt][0] = __float_as_uint(al[mb * SA + k8 + cin]);
                    Al[mt][1] = __float_as_uint(al[(mb + 8) * SA + k8 + cin]);
                    Al[mt][2] = __float_as_uint(al[mb * SA + k8 + cin + 4]);
                    Al[mt][3] = __float_as_uint(al[(mb + 8) * SA + k8 + cin + 4]);
                }
#pragma unroll
                for (int nt = 0; nt < 4; nt++) {
                    int nb = warp_n + nt * 8 + rin;
                    Bh[nt][0] = __float_as_uint(bh[(k8 + cin) * SB + nb]);
                    Bh[nt][1] = __float_as_uint(bh[(k8 + cin + 4) * SB + nb]);
                    Bl[nt][0] = __float_as_uint(bl[(k8 + cin) * SB + nb]);
                    Bl[nt][1] = __float_as_uint(bl[(k8 + cin + 4) * SB + nb]);
                }
#pragma unroll
                for (int mt = 0; mt < 2; mt++)
#pragma unroll
                    for (int nt = 0; nt < 4; nt++) {
                        mma_tf32(acc[mt][nt], Ah[mt][0], Ah[mt][1], Ah[mt][2], Ah[mt][3],
                                 Bh[nt][0], Bh[nt][1]);
                        mma_tf32(acc[mt][nt], Al[mt][0], Al[mt][1], Al[mt][2], Al[mt][3],
                                 Bh[nt][0], Bh[nt][1]);
                        mma_tf32(acc[mt][nt], Ah[mt][0], Ah[mt][1], Ah[mt][2], Ah[mt][3],
                                 Bl[nt][0], Bl[nt][1]);
                    }
            }
        }
        __syncthreads();
    }

    // ---- epilogue ----
#pragma unroll
    for (int mt = 0; mt < 2; mt++) {
#pragma unroll
        for (int nt = 0; nt < 4; nt++) {
            int rg = row0 + warp_m + mt * 16 + rin;
            int cg = col0 + warp_n + nt * 8 + cin * 2;
            if (cg >= N) continue;
            float v0 = acc[mt][nt][0], v1 = acc[mt][nt][1];
            float v2 = acc[mt][nt][2], v3 = acc[mt][nt][3];
            if (act == 1) {
                float b0 = bias[cg], b1 = bias[cg + 1];
                v0 = softplus_f(v0 + b0); v1 = softplus_f(v1 + b1);
                v2 = softplus_f(v2 + b0); v3 = softplus_f(v3 + b1);
            }
            *(float2*)(C + (size_t)rg * ldc + cg)       = make_float2(v0, v1);
            *(float2*)(C + (size_t)(rg + 8) * ldc + cg) = make_float2(v2, v3);
        }
    }
}

// ---------------- causal depthwise conv (width 4) + bias + silu ----------------
__global__ void conv_silu_kernel(const float* __restrict__ xz,
                                 const float* __restrict__ conv_w,
                                 const float* __restrict__ conv_b,
                                 float* __restrict__ u_out)
{
    int idx = blockIdx.x * blockDim.x + threadIdx.x;
    int total = BATCH * LEN * DINNER;
    if (idx >= total) return;
    int d = idx % DINNER;
    int l = (idx / DINNER) % LEN;
    int b = idx / (DINNER * LEN);

    float w0 = conv_w[d * DCONV + 0];
    float w1 = conv_w[d * DCONV + 1];
    float w2 = conv_w[d * DCONV + 2];
    float w3 = conv_w[d * DCONV + 3];

    const float* base = xz + (size_t)b * LEN * 2 * DINNER + d;
    float acc = conv_b[d];
    int ll;
    ll = l - 3; if (ll >= 0) acc = fmaf(base[(size_t)ll * 2 * DINNER], w0, acc);
    ll = l - 2; if (ll >= 0) acc = fmaf(base[(size_t)ll * 2 * DINNER], w1, acc);
    ll = l - 1; if (ll >= 0) acc = fmaf(base[(size_t)ll * 2 * DINNER], w2, acc);
    acc = fmaf(base[(size_t)l * 2 * DINNER], w3, acc);

    u_out[idx] = silu_f(acc);
}

// ---------------- selective scan (8 threads/channel, 2 states each) ----------------
__global__ void scan_kernel(const float* __restrict__ delta,
                            const float* __restrict__ u,
                            const float* __restrict__ xdbl,
                            const float* __restrict__ xz,
                            const float* __restrict__ A,
                            const float* __restrict__ D_skip,
                            float* __restrict__ y)
{
    int tid  = blockIdx.x * blockDim.x + threadIdx.x;
    int t    = tid & 7;
    int chan = tid >> 3;
    if (chan >= BATCH * DINNER) return;
    int b = chan / DINNER;
    int d = chan % DINNER;
    int n0 = t * 2;

    float a0 = A[d * DSTATE + n0];
    float a1 = A[d * DSTATE + n0 + 1];
    float dskip = D_skip[d];

    const float* dptr = delta + (size_t)b * LEN * DINNER + d;
    const float* uptr = u     + (size_t)b * LEN * DINNER + d;
    const float* xd   = xdbl  + (size_t)b * LEN * XDBL_N;
    const float* zptr = xz    + (size_t)b * LEN * 2 * DINNER + DINNER + d;
    float*       yptr = y     + (size_t)b * LEN * DINNER + d;

    float h0 = 0.0f, h1 = 0.0f;

#pragma unroll 2
    for (int l = 0; l < LEN; l++) {
        float dl = dptr[(size_t)l * DINNER];
        float ul = uptr[(size_t)l * DINNER];
        const float* xr = xd + (size_t)l * XDBL_N;
        float Bn0 = xr[DTRANK + n0];
        float Bn1 = xr[DTRANK + n0 + 1];
        float Cn0 = xr[DTRANK + DSTATE + n0];
        float Cn1 = xr[DTRANK + DSTATE + n0 + 1];

        float du = dl * ul;
        h0 = fmaf(__expf(dl * a0), h0, du * Bn0);
        h1 = fmaf(__expf(dl * a1), h1, du * Bn1);

        float part = fmaf(h0, Cn0, h1 * Cn1);
        part += __shfl_xor_sync(0xffffffffu, part, 1);
        part += __shfl_xor_sync(0xffffffffu, part, 2);
        part += __shfl_xor_sync(0xffffffffu, part, 4);

        if (t == 0) {
            float z = zptr[(size_t)l * 2 * DINNER];
            yptr[(size_t)l * DINNER] = (part + ul * dskip) * silu_f(z);
        }
    }
}

// ---------------- launcher ----------------
extern "C" void kernel_launch(void* const* d_in, const int* in_sizes, int n_in,
                              void* d_out, int out_size)
{
    const float* x      = (const float*)d_in[0];
    const float* W_in   = (const float*)d_in[1];
    const float* conv_w = (const float*)d_in[2];
    const float* conv_b = (const float*)d_in[3];
    const float* W_x    = (const float*)d_in[4];
    const float* W_dt   = (const float*)d_in[5];
    const float* b_dt   = (const float*)d_in[6];
    const float* A_log  = (const float*)d_in[7];
    const float* D_skip = (const float*)d_in[8];
    const float* W_out  = (const float*)d_in[9];
    float* out = (float*)d_out;

    float *xz, *u, *xdbl, *delta, *y, *Aneg;
    cudaGetSymbolAddress((void**)&xz,    g_xz);
    cudaGetSymbolAddress((void**)&u,     g_u);
    cudaGetSymbolAddress((void**)&xdbl,  g_xdbl);
    cudaGetSymbolAddress((void**)&delta, g_delta);
    cudaGetSymbolAddress((void**)&y,     g_y);
    cudaGetSymbolAddress((void**)&Aneg,  g_Aneg);

    static bool attr_set = false;
    if (!attr_set) {
        cudaFuncSetAttribute(gemm_tf32, cudaFuncAttributeMaxDynamicSharedMemorySize,
                             GEMM_SMEM_BYTES);
        attr_set = true;
    }

    // A = -exp(A_log)
    neg_exp_kernel<<<(DINNER * DSTATE + 255) / 256, 256>>>(A_log, Aneg, DINNER * DSTATE);

    // 1) xz = x @ W_in   [2048 x 4096], K=1024
    gemm_tf32<<<dim3(4096 / 64, MTOT / 128), 256, GEMM_SMEM_BYTES>>>(
        x, DMODEL, W_in, 2 * DINNER, nullptr, xz, 2 * DINNER, 2 * DINNER, DMODEL, 0);

    // 2) conv + silu -> u
    conv_silu_kernel<<<(MTOT * DINNER + 255) / 256, 256>>>(xz, conv_w, conv_b, u);

    // 3) x_dbl = u @ W_x   [2048 x 96], K=2048
    gemm_tf32<<<dim3(2, MTOT / 128), 256, GEMM_SMEM_BYTES>>>(
        u, DINNER, W_x, XDBL_N, nullptr, xdbl, XDBL_N, XDBL_N, DINNER, 0);

    // 4) delta = softplus(dt @ W_dt + b_dt)   [2048 x 2048], K=64
    gemm_tf32<<<dim3(DINNER / 64, MTOT / 128), 256, GEMM_SMEM_BYTES>>>(
        xdbl, XDBL_N, W_dt, DINNER, b_dt, delta, DINNER, DINNER, DTRANK, 1);

    // 5) selective scan + gating -> y
    scan_kernel<<<(BATCH * DINNER * 8) / 256, 256>>>(delta, u, xdbl, xz, Aneg, D_skip, y);

    // 6) out = y @ W_out   [2048 x 1024], K=2048
    gemm_tf32<<<dim3(DMODEL / 64, MTOT / 128), 256, GEMM_SMEM_BYTES>>>(
        y, DINNER, W_out, DMODEL, nullptr, out, DMODEL, DMODEL, DINNER, 0);
}

// round 5
// speedup vs baseline: 2.0395x; 1.0870x over previous
#include <cuda_runtime.h>
#include <math.h>
#include <cstdint>

// ---------------- problem constants ----------------
#define BATCH   2
#define LEN     1024
#define DMODEL  1024
#define DSTATE  16
#define DCONV   4
#define DINNER  2048
#define DTRANK  64
#define XDBL_N  (DTRANK + 2*DSTATE)   // 96
#define MTOT    (BATCH*LEN)           // 2048
#define NSPLIT  8                     // split-K factor for x_dbl GEMM

// ---------------- scratch (device globals) ----------------
__device__ __align__(256) float g_xz   [(size_t)MTOT * 2 * DINNER];
__device__ __align__(256) float g_u    [(size_t)MTOT * DINNER];
__device__ __align__(256) float g_xdbl [(size_t)MTOT * XDBL_N];
__device__ __align__(256) float g_part [(size_t)NSPLIT * MTOT * XDBL_N];
__device__ __align__(256) float g_delta[(size_t)MTOT * DINNER];
__device__ __align__(256) float g_y    [(size_t)MTOT * DINNER];
__device__ __align__(256) float g_Aneg [DINNER * DSTATE];

// ---------------- helpers ----------------
__device__ __forceinline__ float silu_f(float x)     { return x / (1.0f + __expf(-x)); }
__device__ __forceinline__ float softplus_f(float x) { return fmaxf(x, 0.0f) + log1pf(expf(-fabsf(x))); }

__device__ __forceinline__ float tf32r(float x) {
    uint32_t r;
    asm("cvt.rna.tf32.f32 %0, %1;" : "=r"(r) : "f"(x));
    return __uint_as_float(r);
}
__device__ __forceinline__ uint32_t smem_u32(const void* p) {
    uint32_t a;
    asm("{ .reg .u64 t; cvta.to.shared.u64 t, %1; cvt.u32.u64 %0, t; }" : "=r"(a) : "l"(p));
    return a;
}
__device__ __forceinline__ void cp16(uint32_t dst, const void* src, int bytes) {
    asm volatile("cp.async.cg.shared.global [%0], [%1], 16, %2;"
                 :: "r"(dst), "l"(src), "r"(bytes));
}
#define CP_COMMIT() asm volatile("cp.async.commit_group;")
#define CP_WAIT1()  asm volatile("cp.async.wait_group 1;")

__device__ __forceinline__ void mma_tf32(float c[4],
                                         uint32_t a0, uint32_t a1, uint32_t a2, uint32_t a3,
                                         uint32_t b0, uint32_t b1) {
    asm volatile(
        "mma.sync.aligned.m16n8k8.row.col.f32.tf32.tf32.f32 "
        "{%0,%1,%2,%3}, {%4,%5,%6,%7}, {%8,%9}, {%0,%1,%2,%3};"
        : "+f"(c[0]), "+f"(c[1]), "+f"(c[2]), "+f"(c[3])
        : "r"(a0), "r"(a1), "r"(a2), "r"(a3), "r"(b0), "r"(b1));
}

// ---------------- A precompute ----------------
__global__ void neg_exp_kernel(const float* __restrict__ A_log, float* __restrict__ A, int n) {
    int i = blockIdx.x * blockDim.x + threadIdx.x;
    if (i < n) A[i] = -__expf(A_log[i]);
}

// ================= tf32x3 tensor-core GEMM (cp.async 3-stage) =================
// C[M,N] = A[M,K](lda) @ B[K,N](ldb)   (+ optional bias + softplus)
// Block tile 128x64, BK=16, 256 threads (8 warps as 4x2), warp tile 32x32.
// Raw fp32 in smem; tf32 hi/lo split at fragment-load time.
// Smem per stage: A[128][20] + B[16][72]  = 3712 floats; 3 stages.
#define SA 20
#define SB 72
#define STG_FLOATS 3712
#define GEMM_SMEM_BYTES (3 * STG_FLOATS * 4)   // 44544

__global__ void __launch_bounds__(256, 2)
gemm_tf32(const float* __restrict__ A, int lda,
          const float* __restrict__ B, int ldb,
          const float* __restrict__ bias,
          float* __restrict__ C, int ldc, size_t cstride,
          int N, int Klen, int act)
{
    extern __shared__ float sm[];
    const int tid  = threadIdx.x;
    const int row0 = blockIdx.y * 128;
    const int col0 = blockIdx.x * 64;

    // split-K slab
    const int kbase = blockIdx.z * Klen;
    A += kbase;
    B += (size_t)kbase * ldb;
    C += (size_t)blockIdx.z * cstride;

    const uint32_t smb = smem_u32(sm);

    // copy maps
    const int a_r = tid >> 2;          // 0..63 (and +64)
    const int a_q = (tid & 3) << 2;    // k offset 0,4,8,12
    const int b_k = tid >> 4;          // 0..15
    const int b_q = (tid & 15) << 2;   // n offset 0..60
    const int b_bytes = (col0 + b_q + 4 <= N) ? 16 : 0;

    // compute maps
    const int lane = tid & 31;
    const int rin  = lane >> 2;
    const int cin  = lane & 3;
    const int wid  = tid >> 5;
    const int warp_m = (wid & 3) * 32;
    const int warp_n = (wid >> 2) * 32;

    float acc[2][4][4];
#pragma unroll
    for (int mt = 0; mt < 2; mt++)
#pragma unroll
        for (int nt = 0; nt < 4; nt++)
#pragma unroll
            for (int i = 0; i < 4; i++) acc[mt][nt][i] = 0.0f;

    const int nk = Klen >> 4;

    // ---- async copy of one BK chunk into stage slot ----
    auto issue = [&](int kc) {
        int slot = kc % 3;
        uint32_t ab = smb + slot * (STG_FLOATS * 4);
        uint32_t bb = ab + 2560 * 4;
        int k0 = kc << 4;
        cp16(ab + (a_r * SA + a_q) * 4,
             A + (size_t)(row0 + a_r) * lda + k0 + a_q, 16);
        cp16(ab + ((a_r + 64) * SA + a_q) * 4,
             A + (size_t)(row0 + a_r + 64) * lda + k0 + a_q, 16);
        const float* bs = B + (size_t)(k0 + b_k) * ldb + col0 + b_q;
        cp16(bb + (b_k * SB + b_q) * 4, b_bytes ? bs : B, b_bytes);
    };

    // prologue: stages 0 and 1
    issue(0); CP_COMMIT();
    if (nk > 1) issue(1);
    CP_COMMIT();

    for (int kc = 0; kc < nk; kc++) {
        CP_WAIT1();
        __syncthreads();

        const float* as = sm + (kc % 3) * STG_FLOATS;
        const float* bs = as + 2560;

#pragma unroll
        for (int ks = 0; ks < 2; ks++) {
            int k8 = ks * 8;
            float ar[2][4], br[4][2];
#pragma unroll
            for (int mt = 0; mt < 2; mt++) {
                int mb = warp_m + mt * 16 + rin;
                ar[mt][0] = as[mb * SA + k8 + cin];
                ar[mt][1] = as[(mb + 8) * SA + k8 + cin];
                ar[mt][2] = as[mb * SA + k8 + cin + 4];
                ar[mt][3] = as[(mb + 8) * SA + k8 + cin + 4];
            }
#pragma unroll
            for (int nt = 0; nt < 4; nt++) {
                int nb = warp_n + nt * 8 + rin;
                br[nt][0] = bs[(k8 + cin) * SB + nb];
                br[nt][1] = bs[(k8 + cin + 4) * SB + nb];
            }
            uint32_t Ah[2][4], Al[2][4], Bh[4][2], Bl[4][2];
#pragma unroll
            for (int mt = 0; mt < 2; mt++)
#pragma unroll
                for (int j = 0; j < 4; j++) {
                    float h = tf32r(ar[mt][j]);
                    Ah[mt][j] = __float_as_uint(h);
                    Al[mt][j] = __float_as_uint(tf32r(ar[mt][j] - h));
                }
#pragma unroll
            for (int nt = 0; nt < 4; nt++)
#pragma unroll
                for (int j = 0; j < 2; j++) {
                    float h = tf32r(br[nt][j]);
                    Bh[nt][j] = __float_as_uint(h);
                    Bl[nt][j] = __float_as_uint(tf32r(br[nt][j] - h));
                }
#pragma unroll
            for (int mt = 0; mt < 2; mt++)
#pragma unroll
                for (int nt = 0; nt < 4; nt++) {
                    mma_tf32(acc[mt][nt], Ah[mt][0], Ah[mt][1], Ah[mt][2], Ah[mt][3],
                             Bh[nt][0], Bh[nt][1]);
                    mma_tf32(acc[mt][nt], Al[mt][0], Al[mt][1], Al[mt][2], Al[mt][3],
                             Bh[nt][0], Bh[nt][1]);
                    mma_tf32(acc[mt][nt], Ah[mt][0], Ah[mt][1], Ah[mt][2], Ah[mt][3],
                             Bl[nt][0], Bl[nt][1]);
                }
        }

        if (kc + 2 < nk) issue(kc + 2);
        CP_COMMIT();
    }

    // ---- epilogue ----
#pragma unroll
    for (int mt = 0; mt < 2; mt++) {
#pragma unroll
        for (int nt = 0; nt < 4; nt++) {
            int rg = row0 + warp_m + mt * 16 + rin;
            int cg = col0 + warp_n + nt * 8 + cin * 2;
            if (cg >= N) continue;
            float v0 = acc[mt][nt][0], v1 = acc[mt][nt][1];
            float v2 = acc[mt][nt][2], v3 = acc[mt][nt][3];
            if (act == 1) {
                float b0 = bias[cg], b1 = bias[cg + 1];
                v0 = softplus_f(v0 + b0); v1 = softplus_f(v1 + b1);
                v2 = softplus_f(v2 + b0); v3 = softplus_f(v3 + b1);
            }
            *(float2*)(C + (size_t)rg * ldc + cg)       = make_float2(v0, v1);
            *(float2*)(C + (size_t)(rg + 8) * ldc + cg) = make_float2(v2, v3);
        }
    }
}

// ---------------- split-K reduce: xdbl = sum of NSPLIT slabs ----------------
__global__ void reduce_split(const float* __restrict__ part, float* __restrict__ outp, int n) {
    int i = blockIdx.x * blockDim.x + threadIdx.x;
    if (i >= n) return;
    float s = 0.0f;
#pragma unroll
    for (int k = 0; k < NSPLIT; k++) s += part[(size_t)k * n + i];
    outp[i] = s;
}

// ---------------- causal depthwise conv (width 4) + bias + silu ----------------
__global__ void conv_silu_kernel(const float* __restrict__ xz,
                                 const float* __restrict__ conv_w,
                                 const float* __restrict__ conv_b,
                                 float* __restrict__ u_out)
{
    int idx = blockIdx.x * blockDim.x + threadIdx.x;
    int total = BATCH * LEN * DINNER;
    if (idx >= total) return;
    int d = idx % DINNER;
    int l = (idx / DINNER) % LEN;
    int b = idx / (DINNER * LEN);

    float w0 = conv_w[d * DCONV + 0];
    float w1 = conv_w[d * DCONV + 1];
    float w2 = conv_w[d * DCONV + 2];
    float w3 = conv_w[d * DCONV + 3];

    const float* base = xz + (size_t)b * LEN * 2 * DINNER + d;
    float acc = conv_b[d];
    int ll;
    ll = l - 3; if (ll >= 0) acc = fmaf(base[(size_t)ll * 2 * DINNER], w0, acc);
    ll = l - 2; if (ll >= 0) acc = fmaf(base[(size_t)ll * 2 * DINNER], w1, acc);
    ll = l - 1; if (ll >= 0) acc = fmaf(base[(size_t)ll * 2 * DINNER], w2, acc);
    acc = fmaf(base[(size_t)l * 2 * DINNER], w3, acc);

    u_out[idx] = silu_f(acc);
}

// ---------------- selective scan (8 threads/channel, 2 states each) ----------------
__global__ void scan_kernel(const float* __restrict__ delta,
                            const float* __restrict__ u,
                            const float* __restrict__ xdbl,
                            const float* __restrict__ xz,
                            const float* __restrict__ A,
                            const float* __restrict__ D_skip,
                            float* __restrict__ y)
{
    int tid  = blockIdx.x * blockDim.x + threadIdx.x;
    int t    = tid & 7;
    int chan = tid >> 3;
    if (chan >= BATCH * DINNER) return;
    int b = chan / DINNER;
    int d = chan % DINNER;
    int n0 = t * 2;

    float a0 = A[d * DSTATE + n0];
    float a1 = A[d * DSTATE + n0 + 1];
    float dskip = D_skip[d];

    const float* dptr = delta + (size_t)b * LEN * DINNER + d;
    const float* uptr = u     + (size_t)b * LEN * DINNER + d;
    const float* xd   = xdbl  + (size_t)b * LEN * XDBL_N;
    const float* zptr = xz    + (size_t)b * LEN * 2 * DINNER + DINNER + d;
    float*       yptr = y     + (size_t)b * LEN * DINNER + d;

    float h0 = 0.0f, h1 = 0.0f;

#pragma unroll 2
    for (int l = 0; l < LEN; l++) {
        float dl = dptr[(size_t)l * DINNER];
        float ul = uptr[(size_t)l * DINNER];
        const float* xr = xd + (size_t)l * XDBL_N;
        float Bn0 = xr[DTRANK + n0];
        float Bn1 = xr[DTRANK + n0 + 1];
        float Cn0 = xr[DTRANK + DSTATE + n0];
        float Cn1 = xr[DTRANK + DSTATE + n0 + 1];

        float du = dl * ul;
        h0 = fmaf(__expf(dl * a0), h0, du * Bn0);
        h1 = fmaf(__expf(dl * a1), h1, du * Bn1);

        float part = fmaf(h0, Cn0, h1 * Cn1);
        part += __shfl_xor_sync(0xffffffffu, part, 1);
        part += __shfl_xor_sync(0xffffffffu, part, 2);
        part += __shfl_xor_sync(0xffffffffu, part, 4);

        if (t == 0) {
            float z = zptr[(size_t)l * 2 * DINNER];
            yptr[(size_t)l * DINNER] = (part + ul * dskip) * silu_f(z);
        }
    }
}

// ---------------- launcher ----------------
extern "C" void kernel_launch(void* const* d_in, const int* in_sizes, int n_in,
                              void* d_out, int out_size)
{
    const float* x      = (const float*)d_in[0];
    const float* W_in   = (const float*)d_in[1];
    const float* conv_w = (const float*)d_in[2];
    const float* conv_b = (const float*)d_in[3];
    const float* W_x    = (const float*)d_in[4];
    const float* W_dt   = (const float*)d_in[5];
    const float* b_dt   = (const float*)d_in[6];
    const float* A_log  = (const float*)d_in[7];
    const float* D_skip = (const float*)d_in[8];
    const float* W_out  = (const float*)d_in[9];
    float* out = (float*)d_out;

    float *xz, *u, *xdbl, *part, *delta, *y, *Aneg;
    cudaGetSymbolAddress((void**)&xz,    g_xz);
    cudaGetSymbolAddress((void**)&u,     g_u);
    cudaGetSymbolAddress((void**)&xdbl,  g_xdbl);
    cudaGetSymbolAddress((void**)&part,  g_part);
    cudaGetSymbolAddress((void**)&delta, g_delta);
    cudaGetSymbolAddress((void**)&y,     g_y);
    cudaGetSymbolAddress((void**)&Aneg,  g_Aneg);

    static bool attr_set = false;
    if (!attr_set) {
        cudaFuncSetAttribute(gemm_tf32, cudaFuncAttributeMaxDynamicSharedMemorySize,
                             GEMM_SMEM_BYTES);
        attr_set = true;
    }

    // A = -exp(A_log)
    neg_exp_kernel<<<(DINNER * DSTATE + 255) / 256, 256>>>(A_log, Aneg, DINNER * DSTATE);

    // 1) xz = x @ W_in   [2048 x 4096], K=1024
    gemm_tf32<<<dim3(4096 / 64, MTOT / 128), 256, GEMM_SMEM_BYTES>>>(
        x, DMODEL, W_in, 2 * DINNER, nullptr, xz, 2 * DINNER, 0,
        2 * DINNER, DMODEL, 0);

    // 2) conv + silu -> u
    conv_silu_kernel<<<(MTOT * DINNER + 255) / 256, 256>>>(xz, conv_w, conv_b, u);

    // 3) x_dbl = u @ W_x   [2048 x 96], K=2048 via split-K=8 + reduce
    gemm_tf32<<<dim3(2, MTOT / 128, NSPLIT), 256, GEMM_SMEM_BYTES>>>(
        u, DINNER, W_x, XDBL_N, nullptr, part, XDBL_N, (size_t)MTOT * XDBL_N,
        XDBL_N, DINNER / NSPLIT, 0);
    reduce_split<<<(MTOT * XDBL_N + 255) / 256, 256>>>(part, xdbl, MTOT * XDBL_N);

    // 4) delta = softplus(dt @ W_dt + b_dt)   [2048 x 2048], K=64
    gemm_tf32<<<dim3(DINNER / 64, MTOT / 128), 256, GEMM_SMEM_BYTES>>>(
        xdbl, XDBL_N, W_dt, DINNER, b_dt, delta, DINNER, 0,
        DINNER, DTRANK, 1);

    // 5) selective scan + gating -> y
    scan_kernel<<<(BATCH * DINNER * 8) / 256, 256>>>(delta, u, xdbl, xz, Aneg, D_skip, y);

    // 6) out = y @ W_out   [2048 x 1024], K=2048
    gemm_tf32<<<dim3(DMODEL / 64, MTOT / 128), 256, GEMM_SMEM_BYTES>>>(
        y, DINNER, W_out, DMODEL, nullptr, out, DMODEL, 0,
        DMODEL, DINNER, 0);
}

// round 6
// speedup vs baseline: 2.6812x; 1.3146x over previous
#include <cuda_runtime.h>
#include <math.h>
#include <cstdint>

// ---------------- problem constants ----------------
#define BATCH   2
#define LEN     1024
#define DMODEL  1024
#define DSTATE  16
#define DCONV   4
#define DINNER  2048
#define DTRANK  64
#define XDBL_N  (DTRANK + 2*DSTATE)   // 96
#define MTOT    (BATCH*LEN)           // 2048
#define NSPLIT  8                     // split-K factor for x_dbl GEMM

// ---------------- scratch (device globals) ----------------
__device__ __align__(256) float g_xz   [(size_t)MTOT * 2 * DINNER];
__device__ __align__(256) float g_u    [(size_t)MTOT * DINNER];
__device__ __align__(256) float g_xdbl [(size_t)MTOT * XDBL_N];
__device__ __align__(256) float g_part [(size_t)NSPLIT * MTOT * XDBL_N];
__device__ __align__(256) float g_delta[(size_t)MTOT * DINNER];
__device__ __align__(256) float g_y    [(size_t)MTOT * DINNER];
__device__ __align__(256) float g_Aneg [DINNER * DSTATE];
__device__ int g_flag;

// ---------------- helpers ----------------
__device__ __forceinline__ float silu_f(float x)     { return x / (1.0f + __expf(-x)); }
__device__ __forceinline__ float softplus_f(float x) { return fmaxf(x, 0.0f) + log1pf(expf(-fabsf(x))); }

__device__ __forceinline__ float tf32r(float x) {
    uint32_t r;
    asm("cvt.rna.tf32.f32 %0, %1;" : "=r"(r) : "f"(x));
    return __uint_as_float(r);
}
__device__ __forceinline__ uint32_t smem_u32(const void* p) {
    uint32_t a;
    asm("{ .reg .u64 t; cvta.to.shared.u64 t, %1; cvt.u32.u64 %0, t; }" : "=r"(a) : "l"(p));
    return a;
}
__device__ __forceinline__ void cp16(uint32_t dst, const void* src, int bytes) {
    asm volatile("cp.async.cg.shared.global [%0], [%1], 16, %2;"
                 :: "r"(dst), "l"(src), "r"(bytes));
}
#define CP_COMMIT() asm volatile("cp.async.commit_group;")
#define CP_WAIT1()  asm volatile("cp.async.wait_group 1;")
#define CP_WAIT0()  asm volatile("cp.async.wait_group 0;")

__device__ __forceinline__ void mma_tf32(float c[4],
                                         uint32_t a0, uint32_t a1, uint32_t a2, uint32_t a3,
                                         uint32_t b0, uint32_t b1) {
    asm volatile(
        "mma.sync.aligned.m16n8k8.row.col.f32.tf32.tf32.f32 "
        "{%0,%1,%2,%3}, {%4,%5,%6,%7}, {%8,%9}, {%0,%1,%2,%3};"
        : "+f"(c[0]), "+f"(c[1]), "+f"(c[2]), "+f"(c[3])
        : "r"(a0), "r"(a1), "r"(a2), "r"(a3), "r"(b0), "r"(b1));
}

// ---------------- init / A precompute + structure check ----------------
__global__ void flag_init_kernel() { g_flag = 1; }

__global__ void neg_exp_kernel(const float* __restrict__ A_log, float* __restrict__ A, int n) {
    int i = blockIdx.x * blockDim.x + threadIdx.x;
    if (i < n) {
        float v = -__expf(A_log[i]);
        A[i] = v;
        // structure check: A[d][s] == -(s+1) (within tolerance)
        int s = i & (DSTATE - 1);
        float expect = -(float)(s + 1);
        if (fabsf(v - expect) > 1e-3f * (float)(s + 1))
            atomicAnd(&g_flag, 0);
    }
}

// ================= tf32x3 tensor-core GEMM (cp.async 3-stage) =================
#define SA 20
#define SB 72
#define STG_FLOATS 3712
#define GEMM_SMEM_BYTES (3 * STG_FLOATS * 4)   // 44544

__global__ void __launch_bounds__(256, 2)
gemm_tf32(const float* __restrict__ A, int lda,
          const float* __restrict__ B, int ldb,
          const float* __restrict__ bias,
          float* __restrict__ C, int ldc, size_t cstride,
          int N, int Klen, int act)
{
    extern __shared__ float sm[];
    const int tid  = threadIdx.x;
    const int row0 = blockIdx.y * 128;
    const int col0 = blockIdx.x * 64;

    const int kbase = blockIdx.z * Klen;
    A += kbase;
    B += (size_t)kbase * ldb;
    C += (size_t)blockIdx.z * cstride;

    const uint32_t smb = smem_u32(sm);

    const int a_r = tid >> 2;
    const int a_q = (tid & 3) << 2;
    const int b_k = tid >> 4;
    const int b_q = (tid & 15) << 2;
    const int b_bytes = (col0 + b_q + 4 <= N) ? 16 : 0;

    const int lane = tid & 31;
    const int rin  = lane >> 2;
    const int cin  = lane & 3;
    const int wid  = tid >> 5;
    const int warp_m = (wid & 3) * 32;
    const int warp_n = (wid >> 2) * 32;

    float acc[2][4][4];
#pragma unroll
    for (int mt = 0; mt < 2; mt++)
#pragma unroll
        for (int nt = 0; nt < 4; nt++)
#pragma unroll
            for (int i = 0; i < 4; i++) acc[mt][nt][i] = 0.0f;

    const int nk = Klen >> 4;

    auto issue = [&](int kc) {
        int slot = kc % 3;
        uint32_t ab = smb + slot * (STG_FLOATS * 4);
        uint32_t bb = ab + 2560 * 4;
        int k0 = kc << 4;
        cp16(ab + (a_r * SA + a_q) * 4,
             A + (size_t)(row0 + a_r) * lda + k0 + a_q, 16);
        cp16(ab + ((a_r + 64) * SA + a_q) * 4,
             A + (size_t)(row0 + a_r + 64) * lda + k0 + a_q, 16);
        const float* bs = B + (size_t)(k0 + b_k) * ldb + col0 + b_q;
        cp16(bb + (b_k * SB + b_q) * 4, b_bytes ? bs : B, b_bytes);
    };

    issue(0); CP_COMMIT();
    if (nk > 1) issue(1);
    CP_COMMIT();

    for (int kc = 0; kc < nk; kc++) {
        CP_WAIT1();
        __syncthreads();

        const float* as = sm + (kc % 3) * STG_FLOATS;
        const float* bs = as + 2560;

#pragma unroll
        for (int ks = 0; ks < 2; ks++) {
            int k8 = ks * 8;
            float ar[2][4], br[4][2];
#pragma unroll
            for (int mt = 0; mt < 2; mt++) {
                int mb = warp_m + mt * 16 + rin;
                ar[mt][0] = as[mb * SA + k8 + cin];
                ar[mt][1] = as[(mb + 8) * SA + k8 + cin];
                ar[mt][2] = as[mb * SA + k8 + cin + 4];
                ar[mt][3] = as[(mb + 8) * SA + k8 + cin + 4];
            }
#pragma unroll
            for (int nt = 0; nt < 4; nt++) {
                int nb = warp_n + nt * 8 + rin;
                br[nt][0] = bs[(k8 + cin) * SB + nb];
                br[nt][1] = bs[(k8 + cin + 4) * SB + nb];
            }
            uint32_t Ah[2][4], Al[2][4], Bh[4][2], Bl[4][2];
#pragma unroll
            for (int mt = 0; mt < 2; mt++)
#pragma unroll
                for (int j = 0; j < 4; j++) {
                    float h = tf32r(ar[mt][j]);
                    Ah[mt][j] = __float_as_uint(h);
                    Al[mt][j] = __float_as_uint(tf32r(ar[mt][j] - h));
                }
#pragma unroll
            for (int nt = 0; nt < 4; nt++)
#pragma unroll
                for (int j = 0; j < 2; j++) {
                    float h = tf32r(br[nt][j]);
                    Bh[nt][j] = __float_as_uint(h);
                    Bl[nt][j] = __float_as_uint(tf32r(br[nt][j] - h));
                }
#pragma unroll
            for (int mt = 0; mt < 2; mt++)
#pragma unroll
                for (int nt = 0; nt < 4; nt++) {
                    mma_tf32(acc[mt][nt], Ah[mt][0], Ah[mt][1], Ah[mt][2], Ah[mt][3],
                             Bh[nt][0], Bh[nt][1]);
                    mma_tf32(acc[mt][nt], Al[mt][0], Al[mt][1], Al[mt][2], Al[mt][3],
                             Bh[nt][0], Bh[nt][1]);
                    mma_tf32(acc[mt][nt], Ah[mt][0], Ah[mt][1], Ah[mt][2], Ah[mt][3],
                             Bl[nt][0], Bl[nt][1]);
                }
        }

        if (kc + 2 < nk) issue(kc + 2);
        CP_COMMIT();
    }

#pragma unroll
    for (int mt = 0; mt < 2; mt++) {
#pragma unroll
        for (int nt = 0; nt < 4; nt++) {
            int rg = row0 + warp_m + mt * 16 + rin;
            int cg = col0 + warp_n + nt * 8 + cin * 2;
            if (cg >= N) continue;
            float v0 = acc[mt][nt][0], v1 = acc[mt][nt][1];
            float v2 = acc[mt][nt][2], v3 = acc[mt][nt][3];
            if (act == 1) {
                float b0 = bias[cg], b1 = bias[cg + 1];
                v0 = softplus_f(v0 + b0); v1 = softplus_f(v1 + b1);
                v2 = softplus_f(v2 + b0); v3 = softplus_f(v3 + b1);
            }
            *(float2*)(C + (size_t)rg * ldc + cg)       = make_float2(v0, v1);
            *(float2*)(C + (size_t)(rg + 8) * ldc + cg) = make_float2(v2, v3);
        }
    }
}

// ---------------- split-K reduce ----------------
__global__ void reduce_split(const float* __restrict__ part, float* __restrict__ outp, int n) {
    int i = blockIdx.x * blockDim.x + threadIdx.x;
    if (i >= n) return;
    float s = 0.0f;
#pragma unroll
    for (int k = 0; k < NSPLIT; k++) s += part[(size_t)k * n + i];
    outp[i] = s;
}

// ---------------- causal depthwise conv (width 4) + bias + silu ----------------
__global__ void conv_silu_kernel(const float* __restrict__ xz,
                                 const float* __restrict__ conv_w,
                                 const float* __restrict__ conv_b,
                                 float* __restrict__ u_out)
{
    int idx = blockIdx.x * blockDim.x + threadIdx.x;
    int total = BATCH * LEN * DINNER;
    if (idx >= total) return;
    int d = idx % DINNER;
    int l = (idx / DINNER) % LEN;
    int b = idx / (DINNER * LEN);

    float w0 = conv_w[d * DCONV + 0];
    float w1 = conv_w[d * DCONV + 1];
    float w2 = conv_w[d * DCONV + 2];
    float w3 = conv_w[d * DCONV + 3];

    const float* base = xz + (size_t)b * LEN * 2 * DINNER + d;
    float acc = conv_b[d];
    int ll;
    ll = l - 3; if (ll >= 0) acc = fmaf(base[(size_t)ll * 2 * DINNER], w0, acc);
    ll = l - 2; if (ll >= 0) acc = fmaf(base[(size_t)ll * 2 * DINNER], w1, acc);
    ll = l - 1; if (ll >= 0) acc = fmaf(base[(size_t)ll * 2 * DINNER], w2, acc);
    acc = fmaf(base[(size_t)l * 2 * DINNER], w3, acc);

    u_out[idx] = silu_f(acc);
}

// ================= selective scan v2 =================
// Block: 256 threads = 32 channels x 8 threads (2 states/thread).
// Time processed in 32-step chunks, cp.async double-buffered smem tiles.
// exp count reduced 16x via deltaA_n = q^(n+1), q = exp(delta * A[d][0])
// (A[d][n] = -(n+1) structure, runtime-verified; generic fallback path).
#define SC_T 32
#define SC_C 32
#define SC_TILE (SC_T * SC_C)     // 1024 floats

__global__ void __launch_bounds__(256)
scan_kernel(const float* __restrict__ delta,
            const float* __restrict__ u,
            const float* __restrict__ xdbl,
            const float* __restrict__ xz,
            const float* __restrict__ Aneg,
            const float* __restrict__ D_skip,
            float* __restrict__ y,
            const int* __restrict__ flagp)
{
    __shared__ float sD[2][SC_TILE];
    __shared__ float sU[2][SC_TILE];
    __shared__ float sZ[2][SC_TILE];
    __shared__ float sBC[2][SC_TILE];
    __shared__ float sQ[SC_TILE];
    __shared__ float sY[SC_TILE];
    __shared__ float sSkip[SC_C];
    __shared__ float sAbase[SC_C];

    const int tid = threadIdx.x;
    const int t   = tid & 7;         // state pair 0..7
    const int cl  = tid >> 3;        // channel-local 0..31
    const int g   = blockIdx.x * SC_C;
    const int b   = g >> 11;         // / DINNER
    const int d0  = g & (DINNER - 1);
    const int d   = d0 + cl;

    const int fast = *flagp;

    if (tid < SC_C) {
        sSkip[tid]  = D_skip[d0 + tid];
        sAbase[tid] = Aneg[(d0 + tid) * DSTATE];
    }
    // generic-path coefficients
    float ga0 = Aneg[d * DSTATE + 2 * t];
    float ga1 = Aneg[d * DSTATE + 2 * t + 1];

    const float* dbase = delta + (size_t)b * LEN * DINNER + d0;
    const float* ubase = u     + (size_t)b * LEN * DINNER + d0;
    const float* zbase = xz    + (size_t)b * LEN * 2 * DINNER + DINNER + d0;
    const float* bcb   = xdbl  + (size_t)b * LEN * XDBL_N + DTRANK;
    float*       ybase = y     + (size_t)b * LEN * DINNER + d0;

    const uint32_t aD  = smem_u32(sD);
    const uint32_t aU  = smem_u32(sU);
    const uint32_t aZ  = smem_u32(sZ);
    const uint32_t aBC = smem_u32(sBC);

    // staging map: thread -> (row r, 16B segment s) of a 32x32 tile
    const int pr = tid >> 3;
    const int ps = (tid & 7) << 2;

    auto prefetch = [&](int ch) {
        int buf = ch & 1;
        int l0 = ch * SC_T;
        uint32_t off = (buf * SC_TILE + pr * SC_C + ps) * 4;
        cp16(aD  + off, dbase + (size_t)(l0 + pr) * DINNER + ps, 16);
        cp16(aU  + off, ubase + (size_t)(l0 + pr) * DINNER + ps, 16);
        cp16(aZ  + off, zbase + (size_t)(l0 + pr) * 2 * DINNER + ps, 16);
        cp16(aBC + off, bcb   + (size_t)(l0 + pr) * XDBL_N + ps, 16);
        CP_COMMIT();
    };

    float h0 = 0.0f, h1 = 0.0f;

    prefetch(0);
    const int NC = LEN / SC_T;

    for (int ch = 0; ch < NC; ch++) {
        int buf = ch & 1;
        CP_WAIT0();
        __syncthreads();
        if (ch + 1 < NC) prefetch(ch + 1);

        // q tile: q = exp(delta * A[d][0])
        if (fast) {
#pragma unroll
            for (int i = 0; i < 4; i++) {
                int idx = tid + i * 256;
                sQ[idx] = __expf(sD[buf][idx] * sAbase[idx & (SC_C - 1)]);
            }
        }
        __syncthreads();

        // serial scan over SC_T steps
#pragma unroll 4
        for (int l = 0; l < SC_T; l++) {
            int rowo = l * SC_C;
            float dl = sD[buf][rowo + cl];
            float ul = sU[buf][rowo + cl];
            float2 Bv = *(const float2*)(&sBC[buf][rowo + 2 * t]);
            float2 Cv = *(const float2*)(&sBC[buf][rowo + 16 + 2 * t]);

            float e0p, e1p;
            if (fast) {
                float qq = sQ[rowo + cl];
                float q2 = qq * qq;
                float q4 = q2 * q2;
                float q8 = q4 * q4;
                float p = qq;                 // exponent 2t+1, bit0 always set
                if (t & 1) p *= q2;
                if (t & 2) p *= q4;
                if (t & 4) p *= q8;
                e0p = p;                      // q^(2t+1)
                e1p = p * qq;                 // q^(2t+2)
            } else {
                e0p = __expf(dl * ga0);
                e1p = __expf(dl * ga1);
            }

            float du = dl * ul;
            h0 = fmaf(e0p, h0, du * Bv.x);
            h1 = fmaf(e1p, h1, du * Bv.y);

            float part = fmaf(h0, Cv.x, h1 * Cv.y);
            part += __shfl_xor_sync(0xffffffffu, part, 1);
            part += __shfl_xor_sync(0xffffffffu, part, 2);
            part += __shfl_xor_sync(0xffffffffu, part, 4);
            if (t == 0) sY[rowo + cl] = part;
        }
        __syncthreads();

        // gated coalesced store
        int l0 = ch * SC_T;
#pragma unroll
        for (int i = 0; i < 4; i++) {
            int idx = tid + i * 256;
            int l = idx >> 5, c = idx & (SC_C - 1);
            float ul = sU[buf][idx];
            float zl = sZ[buf][idx];
            float v  = (sY[idx] + ul * sSkip[c]) * silu_f(zl);
            ybase[(size_t)(l0 + l) * DINNER + c] = v;
        }
        __syncthreads();
    }
}

// ---------------- launcher ----------------
extern "C" void kernel_launch(void* const* d_in, const int* in_sizes, int n_in,
                              void* d_out, int out_size)
{
    const float* x      = (const float*)d_in[0];
    const float* W_in   = (const float*)d_in[1];
    const float* conv_w = (const float*)d_in[2];
    const float* conv_b = (const float*)d_in[3];
    const float* W_x    = (const float*)d_in[4];
    const float* W_dt   = (const float*)d_in[5];
    const float* b_dt   = (const float*)d_in[6];
    const float* A_log  = (const float*)d_in[7];
    const float* D_skip = (const float*)d_in[8];
    const float* W_out  = (const float*)d_in[9];
    float* out = (float*)d_out;

    float *xz, *u, *xdbl, *part, *delta, *y, *Aneg;
    int* flagp;
    cudaGetSymbolAddress((void**)&xz,    g_xz);
    cudaGetSymbolAddress((void**)&u,     g_u);
    cudaGetSymbolAddress((void**)&xdbl,  g_xdbl);
    cudaGetSymbolAddress((void**)&part,  g_part);
    cudaGetSymbolAddress((void**)&delta, g_delta);
    cudaGetSymbolAddress((void**)&y,     g_y);
    cudaGetSymbolAddress((void**)&Aneg,  g_Aneg);
    cudaGetSymbolAddress((void**)&flagp, g_flag);

    static bool attr_set = false;
    if (!attr_set) {
        cudaFuncSetAttribute(gemm_tf32, cudaFuncAttributeMaxDynamicSharedMemorySize,
                             GEMM_SMEM_BYTES);
        attr_set = true;
    }

    flag_init_kernel<<<1, 1>>>();
    neg_exp_kernel<<<(DINNER * DSTATE + 255) / 256, 256>>>(A_log, Aneg, DINNER * DSTATE);

    // 1) xz = x @ W_in   [2048 x 4096], K=1024
    gemm_tf32<<<dim3(4096 / 64, MTOT / 128), 256, GEMM_SMEM_BYTES>>>(
        x, DMODEL, W_in, 2 * DINNER, nullptr, xz, 2 * DINNER, 0,
        2 * DINNER, DMODEL, 0);

    // 2) conv + silu -> u
    conv_silu_kernel<<<(MTOT * DINNER + 255) / 256, 256>>>(xz, conv_w, conv_b, u);

    // 3) x_dbl = u @ W_x   [2048 x 96], K=2048 via split-K=8 + reduce
    gemm_tf32<<<dim3(2, MTOT / 128, NSPLIT), 256, GEMM_SMEM_BYTES>>>(
        u, DINNER, W_x, XDBL_N, nullptr, part, XDBL_N, (size_t)MTOT * XDBL_N,
        XDBL_N, DINNER / NSPLIT, 0);
    reduce_split<<<(MTOT * XDBL_N + 255) / 256, 256>>>(part, xdbl, MTOT * XDBL_N);

    // 4) delta = softplus(dt @ W_dt + b_dt)   [2048 x 2048], K=64
    gemm_tf32<<<dim3(DINNER / 64, MTOT / 128), 256, GEMM_SMEM_BYTES>>>(
        xdbl, XDBL_N, W_dt, DINNER, b_dt, delta, DINNER, 0,
        DINNER, DTRANK, 1);

    // 5) selective scan + gating -> y
    scan_kernel<<<(BATCH * DINNER) / SC_C, 256>>>(delta, u, xdbl, xz, Aneg, D_skip, y, flagp);

    // 6) out = y @ W_out   [2048 x 1024], K=2048
    gemm_tf32<<<dim3(DMODEL / 64, MTOT / 128), 256, GEMM_SMEM_BYTES>>>(
        y, DINNER, W_out, DMODEL, nullptr, out, DMODEL, 0,
        DMODEL, DINNER, 0);
}

// round 7
// speedup vs baseline: 4.4341x; 1.6538x over previous
#include <cuda_runtime.h>
#include <math.h>
#include <cstdint>

// ---------------- problem constants ----------------
#define BATCH   2
#define LEN     1024
#define DMODEL  1024
#define DSTATE  16
#define DCONV   4
#define DINNER  2048
#define DTRANK  64
#define XDBL_N  (DTRANK + 2*DSTATE)   // 96
#define MTOT    (BATCH*LEN)           // 2048
#define NSPLIT  8                     // split-K factor for x_dbl GEMM
#define NT      8                     // time chunks for parallel scan
#define CHUNK_L (LEN/NT)              // 128
#define NCH     (BATCH*DINNER)        // 4096 channels

// ---------------- scratch (device globals) ----------------
__device__ __align__(256) float g_xz   [(size_t)MTOT * 2 * DINNER];
__device__ __align__(256) float g_u    [(size_t)MTOT * DINNER];
__device__ __align__(256) float g_xdbl [(size_t)MTOT * XDBL_N];
__device__ __align__(256) float g_part [(size_t)NSPLIT * MTOT * XDBL_N];
__device__ __align__(256) float g_delta[(size_t)MTOT * DINNER];
__device__ __align__(256) float g_y    [(size_t)MTOT * DINNER];
__device__ __align__(256) float g_qcum [(size_t)MTOT * DINNER];
__device__ __align__(256) float g_hend [(size_t)NT * DSTATE * NCH];
__device__ __align__(256) float g_hstart[(size_t)NT * DSTATE * NCH];
__device__ __align__(256) float g_qct  [(size_t)NT * NCH];
__device__ __align__(256) float g_Aneg [DINNER * DSTATE];
__device__ int g_flag;

// ---------------- helpers ----------------
__device__ __forceinline__ float silu_f(float x)     { return x / (1.0f + __expf(-x)); }
__device__ __forceinline__ float softplus_f(float x) { return fmaxf(x, 0.0f) + log1pf(expf(-fabsf(x))); }

__device__ __forceinline__ float tf32r(float x) {
    uint32_t r;
    asm("cvt.rna.tf32.f32 %0, %1;" : "=r"(r) : "f"(x));
    return __uint_as_float(r);
}
__device__ __forceinline__ uint32_t smem_u32(const void* p) {
    uint32_t a;
    asm("{ .reg .u64 t; cvta.to.shared.u64 t, %1; cvt.u32.u64 %0, t; }" : "=r"(a) : "l"(p));
    return a;
}
__device__ __forceinline__ void cp16(uint32_t dst, const void* src, int bytes) {
    asm volatile("cp.async.cg.shared.global [%0], [%1], 16, %2;"
                 :: "r"(dst), "l"(src), "r"(bytes));
}
#define CP_COMMIT() asm volatile("cp.async.commit_group;")
#define CP_WAIT1()  asm volatile("cp.async.wait_group 1;")
#define CP_WAIT0()  asm volatile("cp.async.wait_group 0;")

__device__ __forceinline__ void mma_tf32(float c[4],
                                         uint32_t a0, uint32_t a1, uint32_t a2, uint32_t a3,
                                         uint32_t b0, uint32_t b1) {
    asm volatile(
        "mma.sync.aligned.m16n8k8.row.col.f32.tf32.tf32.f32 "
        "{%0,%1,%2,%3}, {%4,%5,%6,%7}, {%8,%9}, {%0,%1,%2,%3};"
        : "+f"(c[0]), "+f"(c[1]), "+f"(c[2]), "+f"(c[3])
        : "r"(a0), "r"(a1), "r"(a2), "r"(a3), "r"(b0), "r"(b1));
}

// ---------------- init / A precompute + structure check ----------------
__global__ void flag_init_kernel() { g_flag = 1; }

__global__ void neg_exp_kernel(const float* __restrict__ A_log, float* __restrict__ A, int n) {
    int i = blockIdx.x * blockDim.x + threadIdx.x;
    if (i < n) {
        float v = -__expf(A_log[i]);
        A[i] = v;
        int s = i & (DSTATE - 1);
        float expect = -(float)(s + 1);
        if (fabsf(v - expect) > 1e-3f * (float)(s + 1))
            atomicAnd(&g_flag, 0);
    }
}

// ================= tf32x3 tensor-core GEMM (cp.async 3-stage) =================
#define SA 20
#define SB 72
#define STG_FLOATS 3712
#define GEMM_SMEM_BYTES (3 * STG_FLOATS * 4)   // 44544

__global__ void __launch_bounds__(256, 2)
gemm_tf32(const float* __restrict__ A, int lda,
          const float* __restrict__ B, int ldb,
          const float* __restrict__ bias,
          float* __restrict__ C, int ldc, size_t cstride,
          int N, int Klen, int act)
{
    extern __shared__ float sm[];
    const int tid  = threadIdx.x;
    const int row0 = blockIdx.y * 128;
    const int col0 = blockIdx.x * 64;

    const int kbase = blockIdx.z * Klen;
    A += kbase;
    B += (size_t)kbase * ldb;
    C += (size_t)blockIdx.z * cstride;

    const uint32_t smb = smem_u32(sm);

    const int a_r = tid >> 2;
    const int a_q = (tid & 3) << 2;
    const int b_k = tid >> 4;
    const int b_q = (tid & 15) << 2;
    const int b_bytes = (col0 + b_q + 4 <= N) ? 16 : 0;

    const int lane = tid & 31;
    const int rin  = lane >> 2;
    const int cin  = lane & 3;
    const int wid  = tid >> 5;
    const int warp_m = (wid & 3) * 32;
    const int warp_n = (wid >> 2) * 32;

    float acc[2][4][4];
#pragma unroll
    for (int mt = 0; mt < 2; mt++)
#pragma unroll
        for (int nt = 0; nt < 4; nt++)
#pragma unroll
            for (int i = 0; i < 4; i++) acc[mt][nt][i] = 0.0f;

    const int nk = Klen >> 4;

    auto issue = [&](int kc) {
        int slot = kc % 3;
        uint32_t ab = smb + slot * (STG_FLOATS * 4);
        uint32_t bb = ab + 2560 * 4;
        int k0 = kc << 4;
        cp16(ab + (a_r * SA + a_q) * 4,
             A + (size_t)(row0 + a_r) * lda + k0 + a_q, 16);
        cp16(ab + ((a_r + 64) * SA + a_q) * 4,
             A + (size_t)(row0 + a_r + 64) * lda + k0 + a_q, 16);
        const float* bs = B + (size_t)(k0 + b_k) * ldb + col0 + b_q;
        cp16(bb + (b_k * SB + b_q) * 4, b_bytes ? bs : B, b_bytes);
    };

    issue(0); CP_COMMIT();
    if (nk > 1) issue(1);
    CP_COMMIT();

    for (int kc = 0; kc < nk; kc++) {
        CP_WAIT1();
        __syncthreads();

        const float* as = sm + (kc % 3) * STG_FLOATS;
        const float* bs = as + 2560;

#pragma unroll
        for (int ks = 0; ks < 2; ks++) {
            int k8 = ks * 8;
            float ar[2][4], br[4][2];
#pragma unroll
            for (int mt = 0; mt < 2; mt++) {
                int mb = warp_m + mt * 16 + rin;
                ar[mt][0] = as[mb * SA + k8 + cin];
                ar[mt][1] = as[(mb + 8) * SA + k8 + cin];
                ar[mt][2] = as[mb * SA + k8 + cin + 4];
                ar[mt][3] = as[(mb + 8) * SA + k8 + cin + 4];
            }
#pragma unroll
            for (int nt = 0; nt < 4; nt++) {
                int nb = warp_n + nt * 8 + rin;
                br[nt][0] = bs[(k8 + cin) * SB + nb];
                br[nt][1] = bs[(k8 + cin + 4) * SB + nb];
            }
            uint32_t Ah[2][4], Al[2][4], Bh[4][2], Bl[4][2];
#pragma unroll
            for (int mt = 0; mt < 2; mt++)
#pragma unroll
                for (int j = 0; j < 4; j++) {
                    float h = tf32r(ar[mt][j]);
                    Ah[mt][j] = __float_as_uint(h);
                    Al[mt][j] = __float_as_uint(tf32r(ar[mt][j] - h));
                }
#pragma unroll
            for (int nt = 0; nt < 4; nt++)
#pragma unroll
                for (int j = 0; j < 2; j++) {
                    float h = tf32r(br[nt][j]);
                    Bh[nt][j] = __float_as_uint(h);
                    Bl[nt][j] = __float_as_uint(tf32r(br[nt][j] - h));
                }
#pragma unroll
            for (int mt = 0; mt < 2; mt++)
#pragma unroll
                for (int nt = 0; nt < 4; nt++) {
                    mma_tf32(acc[mt][nt], Ah[mt][0], Ah[mt][1], Ah[mt][2], Ah[mt][3],
                             Bh[nt][0], Bh[nt][1]);
                    mma_tf32(acc[mt][nt], Al[mt][0], Al[mt][1], Al[mt][2], Al[mt][3],
                             Bh[nt][0], Bh[nt][1]);
                    mma_tf32(acc[mt][nt], Ah[mt][0], Ah[mt][1], Ah[mt][2], Ah[mt][3],
                             Bl[nt][0], Bl[nt][1]);
                }
        }

        if (kc + 2 < nk) issue(kc + 2);
        CP_COMMIT();
    }

#pragma unroll
    for (int mt = 0; mt < 2; mt++) {
#pragma unroll
        for (int nt = 0; nt < 4; nt++) {
            int rg = row0 + warp_m + mt * 16 + rin;
            int cg = col0 + warp_n + nt * 8 + cin * 2;
            if (cg >= N) continue;
            float v0 = acc[mt][nt][0], v1 = acc[mt][nt][1];
            float v2 = acc[mt][nt][2], v3 = acc[mt][nt][3];
            if (act == 1) {
                float b0 = bias[cg], b1 = bias[cg + 1];
                v0 = softplus_f(v0 + b0); v1 = softplus_f(v1 + b1);
                v2 = softplus_f(v2 + b0); v3 = softplus_f(v3 + b1);
            }
            *(float2*)(C + (size_t)rg * ldc + cg)       = make_float2(v0, v1);
            *(float2*)(C + (size_t)(rg + 8) * ldc + cg) = make_float2(v2, v3);
        }
    }
}

// ---------------- split-K reduce ----------------
__global__ void reduce_split(const float* __restrict__ part, float* __restrict__ outp, int n) {
    int i = blockIdx.x * blockDim.x + threadIdx.x;
    if (i >= n) return;
    float s = 0.0f;
#pragma unroll
    for (int k = 0; k < NSPLIT; k++) s += part[(size_t)k * n + i];
    outp[i] = s;
}

// ---------------- causal depthwise conv (width 4) + bias + silu ----------------
__global__ void conv_silu_kernel(const float* __restrict__ xz,
                                 const float* __restrict__ conv_w,
                                 const float* __restrict__ conv_b,
                                 float* __restrict__ u_out)
{
    int idx = blockIdx.x * blockDim.x + threadIdx.x;
    int total = BATCH * LEN * DINNER;
    if (idx >= total) return;
    int d = idx % DINNER;
    int l = (idx / DINNER) % LEN;
    int b = idx / (DINNER * LEN);

    float w0 = conv_w[d * DCONV + 0];
    float w1 = conv_w[d * DCONV + 1];
    float w2 = conv_w[d * DCONV + 2];
    float w3 = conv_w[d * DCONV + 3];

    const float* base = xz + (size_t)b * LEN * 2 * DINNER + d;
    float acc = conv_b[d];
    int ll;
    ll = l - 3; if (ll >= 0) acc = fmaf(base[(size_t)ll * 2 * DINNER], w0, acc);
    ll = l - 2; if (ll >= 0) acc = fmaf(base[(size_t)ll * 2 * DINNER], w1, acc);
    ll = l - 1; if (ll >= 0) acc = fmaf(base[(size_t)ll * 2 * DINNER], w2, acc);
    acc = fmaf(base[(size_t)l * 2 * DINNER], w3, acc);

    u_out[idx] = silu_f(acc);
}

// ================= parallel selective scan (fast path, 3 passes) =================
// Pass 1: grid (128 chan-groups, NT chunks), 256 thr = 32 ch x 8 thr.
// Scans its chunk from h=0, emits ungated y_local + running qcum, carries h_end/qc.
#define SC_T 32
#define SC_C 32
#define SC_TILE (SC_T * SC_C)

__global__ void __launch_bounds__(256)
scan_pass1(const float* __restrict__ delta,
           const float* __restrict__ u,
           const float* __restrict__ xdbl,
           const float* __restrict__ Aneg,
           float* __restrict__ y_local,
           float* __restrict__ qcum_out,
           float* __restrict__ h_end,
           float* __restrict__ qc_tot,
           const int* __restrict__ flagp)
{
    if (!*flagp) return;

    __shared__ float sD[2][SC_TILE];
    __shared__ float sU[2][SC_TILE];
    __shared__ float sBC[2][SC_TILE];
    __shared__ float sQ[SC_TILE];
    __shared__ float sY[SC_TILE];
    __shared__ float sQC[SC_TILE];
    __shared__ float sAbase[SC_C];

    const int tid = threadIdx.x;
    const int t   = tid & 7;
    const int cl  = tid >> 3;
    const int g   = blockIdx.x * SC_C;
    const int k   = blockIdx.y;            // time chunk
    const int b   = g >> 11;
    const int d0  = g & (DINNER - 1);
    const int l0  = k * CHUNK_L;

    if (tid < SC_C) sAbase[tid] = Aneg[(d0 + tid) * DSTATE];

    const float* dbase = delta + ((size_t)b * LEN + l0) * DINNER + d0;
    const float* ubase = u     + ((size_t)b * LEN + l0) * DINNER + d0;
    const float* bcb   = xdbl  + ((size_t)b * LEN + l0) * XDBL_N + DTRANK;
    float* ybase = y_local  + ((size_t)b * LEN + l0) * DINNER + d0;
    float* qbase = qcum_out + ((size_t)b * LEN + l0) * DINNER + d0;

    const uint32_t aD  = smem_u32(sD);
    const uint32_t aU  = smem_u32(sU);
    const uint32_t aBC = smem_u32(sBC);

    const int pr = tid >> 3;
    const int ps = (tid & 7) << 2;

    auto prefetch = [&](int sub) {
        int buf = sub & 1;
        int r = sub * SC_T + pr;
        uint32_t off = (buf * SC_TILE + pr * SC_C + ps) * 4;
        cp16(aD  + off, dbase + (size_t)r * DINNER + ps, 16);
        cp16(aU  + off, ubase + (size_t)r * DINNER + ps, 16);
        cp16(aBC + off, bcb   + (size_t)r * XDBL_N + ps, 16);
        CP_COMMIT();
    };

    float h0 = 0.0f, h1 = 0.0f, qcum = 1.0f;

    prefetch(0);
    const int NS = CHUNK_L / SC_T;   // 4

    for (int sub = 0; sub < NS; sub++) {
        int buf = sub & 1;
        CP_WAIT0();
        __syncthreads();
        if (sub + 1 < NS) prefetch(sub + 1);

#pragma unroll
        for (int i = 0; i < 4; i++) {
            int idx = tid + i * 256;
            sQ[idx] = __expf(sD[buf][idx] * sAbase[idx & (SC_C - 1)]);
        }
        __syncthreads();

#pragma unroll 4
        for (int l = 0; l < SC_T; l++) {
            int rowo = l * SC_C;
            float dl = sD[buf][rowo + cl];
            float ul = sU[buf][rowo + cl];
            float2 Bv = *(const float2*)(&sBC[buf][rowo + 2 * t]);
            float2 Cv = *(const float2*)(&sBC[buf][rowo + 16 + 2 * t]);

            float qq = sQ[rowo + cl];
            float q2 = qq * qq;
            float q4 = q2 * q2;
            float q8 = q4 * q4;
            float p = qq;
            if (t & 1) p *= q2;
            if (t & 2) p *= q4;
            if (t & 4) p *= q8;
            float e0p = p;
            float e1p = p * qq;

            qcum *= qq;

            float du = dl * ul;
            h0 = fmaf(e0p, h0, du * Bv.x);
            h1 = fmaf(e1p, h1, du * Bv.y);

            float part = fmaf(h0, Cv.x, h1 * Cv.y);
            part += __shfl_xor_sync(0xffffffffu, part, 1);
            part += __shfl_xor_sync(0xffffffffu, part, 2);
            part += __shfl_xor_sync(0xffffffffu, part, 4);
            if (t == 0) {
                sY[rowo + cl]  = part;
                sQC[rowo + cl] = qcum;
            }
        }
        __syncthreads();

        int r0 = sub * SC_T;
#pragma unroll
        for (int i = 0; i < 4; i++) {
            int idx = tid + i * 256;
            int l = idx >> 5, c = idx & (SC_C - 1);
            ybase[(size_t)(r0 + l) * DINNER + c] = sY[idx];
            qbase[(size_t)(r0 + l) * DINNER + c] = sQC[idx];
        }
        __syncthreads();
    }

    // carries: h_end layout [k][n][bd], qc_tot [k][bd]
    int bd = b * DINNER + d0 + cl;
    h_end[((size_t)k * DSTATE + 2 * t)     * NCH + bd] = h0;
    h_end[((size_t)k * DSTATE + 2 * t + 1) * NCH + bd] = h1;
    if (t == 0) qc_tot[(size_t)k * NCH + bd] = qcum;
}

// Pass 2: prefix over chunk carries. One thread per (n, bd). idx = n*NCH + bd.
__global__ void scan_pass2(const float* __restrict__ h_end,
                           const float* __restrict__ qc_tot,
                           float* __restrict__ h_start,
                           const int* __restrict__ flagp)
{
    if (!*flagp) return;
    int idx = blockIdx.x * blockDim.x + threadIdx.x;
    if (idx >= DSTATE * NCH) return;
    int n  = idx / NCH;
    int bd = idx - n * NCH;
    int e  = n + 1;

    float hs = 0.0f;
#pragma unroll
    for (int k = 0; k < NT; k++) {
        h_start[((size_t)k * DSTATE + n) * NCH + bd] = hs;
        float qc = qc_tot[(size_t)k * NCH + bd];
        float q2 = qc * qc, q4 = q2 * q2, q8 = q4 * q4, q16 = q8 * q8;
        float p = 1.0f;
        if (e & 1) p *= qc;
        if (e & 2) p *= q2;
        if (e & 4) p *= q4;
        if (e & 8) p *= q8;
        if (e & 16) p *= q16;
        hs = fmaf(p, hs, h_end[((size_t)k * DSTATE + n) * NCH + bd]);
    }
}

// Pass 3: elementwise correction + gating. One thread per (b,l,d).
__global__ void __launch_bounds__(256)
scan_pass3(float* __restrict__ y,             // in: y_local, out: gated y
           const float* __restrict__ qcum,
           const float* __restrict__ h_start,
           const float* __restrict__ xdbl,
           const float* __restrict__ u,
           const float* __restrict__ xz,
           const float* __restrict__ D_skip,
           const int* __restrict__ flagp)
{
    if (!*flagp) return;
    int idx = blockIdx.x * blockDim.x + threadIdx.x;
    if (idx >= MTOT * DINNER) return;
    int d  = idx & (DINNER - 1);
    int bl = idx >> 11;              // b*LEN + l
    int l  = bl & (LEN - 1);
    int b  = bl >> 10;
    int k  = l >> 7;                 // chunk
    int bd = b * DINNER + d;

    float q = qcum[idx];
    const float* Crow = xdbl + (size_t)bl * XDBL_N + DTRANK + DSTATE;
    const float* hs   = h_start + (size_t)k * DSTATE * NCH + bd;

    float acc = 0.0f;
    float pn = q;
#pragma unroll
    for (int n = 0; n < DSTATE; n++) {
        acc = fmaf(Crow[n] * hs[(size_t)n * NCH], pn, acc);
        pn *= q;
    }

    float ul = u[idx];
    float zl = xz[(size_t)bl * 2 * DINNER + DINNER + d];
    float yl = y[idx];
    y[idx] = (yl + acc + ul * D_skip[d]) * silu_f(zl);
}

// ---------------- monolithic fallback scan (generic A; runs only if !fast) ------
__global__ void __launch_bounds__(256)
scan_fallback(const float* __restrict__ delta,
              const float* __restrict__ u,
              const float* __restrict__ xdbl,
              const float* __restrict__ xz,
              const float* __restrict__ Aneg,
              const float* __restrict__ D_skip,
              float* __restrict__ y,
              const int* __restrict__ flagp)
{
    if (*flagp) return;
    int tid  = blockIdx.x * blockDim.x + threadIdx.x;
    int t    = tid & 7;
    int chan = tid >> 3;
    if (chan >= NCH) return;
    int b = chan / DINNER;
    int d = chan % DINNER;
    int n0 = t * 2;

    float a0 = Aneg[d * DSTATE + n0];
    float a1 = Aneg[d * DSTATE + n0 + 1];
    float dskip = D_skip[d];

    const float* dptr = delta + (size_t)b * LEN * DINNER + d;
    const float* uptr = u     + (size_t)b * LEN * DINNER + d;
    const float* xd   = xdbl  + (size_t)b * LEN * XDBL_N;
    const float* zptr = xz    + (size_t)b * LEN * 2 * DINNER + DINNER + d;
    float*       yptr = y     + (size_t)b * LEN * DINNER + d;

    float h0 = 0.0f, h1 = 0.0f;
#pragma unroll 2
    for (int l = 0; l < LEN; l++) {
        float dl = dptr[(size_t)l * DINNER];
        float ul = uptr[(size_t)l * DINNER];
        const float* xr = xd + (size_t)l * XDBL_N;
        float Bn0 = xr[DTRANK + n0];
        float Bn1 = xr[DTRANK + n0 + 1];
        float Cn0 = xr[DTRANK + DSTATE + n0];
        float Cn1 = xr[DTRANK + DSTATE + n0 + 1];

        float du = dl * ul;
        h0 = fmaf(__expf(dl * a0), h0, du * Bn0);
        h1 = fmaf(__expf(dl * a1), h1, du * Bn1);

        float part = fmaf(h0, Cn0, h1 * Cn1);
        part += __shfl_xor_sync(0xffffffffu, part, 1);
        part += __shfl_xor_sync(0xffffffffu, part, 2);
        part += __shfl_xor_sync(0xffffffffu, part, 4);

        if (t == 0) {
            float z = zptr[(size_t)l * 2 * DINNER];
            yptr[(size_t)l * DINNER] = (part + ul * dskip) * silu_f(z);
        }
    }
}

// ---------------- launcher ----------------
extern "C" void kernel_launch(void* const* d_in, const int* in_sizes, int n_in,
                              void* d_out, int out_size)
{
    const float* x      = (const float*)d_in[0];
    const float* W_in   = (const float*)d_in[1];
    const float* conv_w = (const float*)d_in[2];
    const float* conv_b = (const float*)d_in[3];
    const float* W_x    = (const float*)d_in[4];
    const float* W_dt   = (const float*)d_in[5];
    const float* b_dt   = (const float*)d_in[6];
    const float* A_log  = (const float*)d_in[7];
    const float* D_skip = (const float*)d_in[8];
    const float* W_out  = (const float*)d_in[9];
    float* out = (float*)d_out;

    float *xz, *u, *xdbl, *part, *delta, *y, *qcum, *hend, *hstart, *qct, *Aneg;
    int* flagp;
    cudaGetSymbolAddress((void**)&xz,     g_xz);
    cudaGetSymbolAddress((void**)&u,      g_u);
    cudaGetSymbolAddress((void**)&xdbl,   g_xdbl);
    cudaGetSymbolAddress((void**)&part,   g_part);
    cudaGetSymbolAddress((void**)&delta,  g_delta);
    cudaGetSymbolAddress((void**)&y,      g_y);
    cudaGetSymbolAddress((void**)&qcum,   g_qcum);
    cudaGetSymbolAddress((void**)&hend,   g_hend);
    cudaGetSymbolAddress((void**)&hstart, g_hstart);
    cudaGetSymbolAddress((void**)&qct,    g_qct);
    cudaGetSymbolAddress((void**)&Aneg,   g_Aneg);
    cudaGetSymbolAddress((void**)&flagp,  g_flag);

    static bool attr_set = false;
    if (!attr_set) {
        cudaFuncSetAttribute(gemm_tf32, cudaFuncAttributeMaxDynamicSharedMemorySize,
                             GEMM_SMEM_BYTES);
        attr_set = true;
    }

    flag_init_kernel<<<1, 1>>>();
    neg_exp_kernel<<<(DINNER * DSTATE + 255) / 256, 256>>>(A_log, Aneg, DINNER * DSTATE);

    // 1) xz = x @ W_in   [2048 x 4096], K=1024
    gemm_tf32<<<dim3(4096 / 64, MTOT / 128), 256, GEMM_SMEM_BYTES>>>(
        x, DMODEL, W_in, 2 * DINNER, nullptr, xz, 2 * DINNER, 0,
        2 * DINNER, DMODEL, 0);

    // 2) conv + silu -> u
    conv_silu_kernel<<<(MTOT * DINNER + 255) / 256, 256>>>(xz, conv_w, conv_b, u);

    // 3) x_dbl = u @ W_x   [2048 x 96], K=2048 via split-K=8 + reduce
    gemm_tf32<<<dim3(2, MTOT / 128, NSPLIT), 256, GEMM_SMEM_BYTES>>>(
        u, DINNER, W_x, XDBL_N, nullptr, part, XDBL_N, (size_t)MTOT * XDBL_N,
        XDBL_N, DINNER / NSPLIT, 0);
    reduce_split<<<(MTOT * XDBL_N + 255) / 256, 256>>>(part, xdbl, MTOT * XDBL_N);

    // 4) delta = softplus(dt @ W_dt + b_dt)   [2048 x 2048], K=64
    gemm_tf32<<<dim3(DINNER / 64, MTOT / 128), 256, GEMM_SMEM_BYTES>>>(
        xdbl, XDBL_N, W_dt, DINNER, b_dt, delta, DINNER, 0,
        DINNER, DTRANK, 1);

    // 5) selective scan: 3-pass parallel-in-time (fast) + monolithic fallback
    scan_pass1<<<dim3(NCH / SC_C, NT), 256>>>(delta, u, xdbl, Aneg, y, qcum,
                                              hend, qct, flagp);
    scan_pass2<<<(DSTATE * NCH + 255) / 256, 256>>>(hend, qct, hstart, flagp);
    scan_pass3<<<(MTOT * DINNER + 255) / 256, 256>>>(y, qcum, hstart, xdbl, u,
                                                     xz, D_skip, flagp);
    scan_fallback<<<(NCH * 8) / 256, 256>>>(delta, u, xdbl, xz, Aneg, D_skip, y, flagp);

    // 6) out = y @ W_out   [2048 x 1024], K=2048
    gemm_tf32<<<dim3(DMODEL / 64, MTOT / 128), 256, GEMM_SMEM_BYTES>>>(
        y, DINNER, W_out, DMODEL, nullptr, out, DMODEL, 0,
        DMODEL, DINNER, 0);
}

// round 8
// speedup vs baseline: 4.6081x; 1.0393x over previous
#include <cuda_runtime.h>
#include <math.h>
#include <cstdint>

// ---------------- problem constants ----------------
#define BATCH   2
#define LEN     1024
#define DMODEL  1024
#define DSTATE  16
#define DCONV   4
#define DINNER  2048
#define DTRANK  64
#define XDBL_N  (DTRANK + 2*DSTATE)   // 96
#define MTOT    (BATCH*LEN)           // 2048
#define NSPLIT  8                     // split-K factor for x_dbl GEMM
#define NT      16                    // time chunks for parallel scan
#define CHUNK_L (LEN/NT)              // 64
#define CHUNK_SHIFT 6
#define NCH     (BATCH*DINNER)        // 4096 channels
#define P1_C    256                   // channels per pass1 block

// ---------------- scratch (device globals) ----------------
__device__ __align__(256) float g_xz   [(size_t)MTOT * 2 * DINNER];
__device__ __align__(256) float g_u    [(size_t)MTOT * DINNER];
__device__ __align__(256) float g_xdbl [(size_t)MTOT * XDBL_N];
__device__ __align__(256) float g_part [(size_t)NSPLIT * MTOT * XDBL_N];
__device__ __align__(256) float g_delta[(size_t)MTOT * DINNER];
__device__ __align__(256) float g_y    [(size_t)MTOT * DINNER];
__device__ __align__(256) float g_qcum [(size_t)MTOT * DINNER];
__device__ __align__(256) float g_hend [(size_t)NT * DSTATE * NCH];
__device__ __align__(256) float g_hstart[(size_t)NT * DSTATE * NCH];
__device__ __align__(256) float g_qct  [(size_t)NT * NCH];
__device__ __align__(256) float g_Aneg [DINNER * DSTATE];
__device__ int g_flag;

// ---------------- helpers ----------------
__device__ __forceinline__ float silu_f(float x)     { return x / (1.0f + __expf(-x)); }
__device__ __forceinline__ float softplus_f(float x) { return fmaxf(x, 0.0f) + log1pf(expf(-fabsf(x))); }

__device__ __forceinline__ float tf32r(float x) {
    uint32_t r;
    asm("cvt.rna.tf32.f32 %0, %1;" : "=r"(r) : "f"(x));
    return __uint_as_float(r);
}
__device__ __forceinline__ uint32_t smem_u32(const void* p) {
    uint32_t a;
    asm("{ .reg .u64 t; cvta.to.shared.u64 t, %1; cvt.u32.u64 %0, t; }" : "=r"(a) : "l"(p));
    return a;
}
__device__ __forceinline__ void cp16(uint32_t dst, const void* src, int bytes) {
    asm volatile("cp.async.cg.shared.global [%0], [%1], 16, %2;"
                 :: "r"(dst), "l"(src), "r"(bytes));
}
#define CP_COMMIT() asm volatile("cp.async.commit_group;")
#define CP_WAIT1()  asm volatile("cp.async.wait_group 1;")
#define CP_WAIT0()  asm volatile("cp.async.wait_group 0;")

__device__ __forceinline__ void mma_tf32(float c[4],
                                         uint32_t a0, uint32_t a1, uint32_t a2, uint32_t a3,
                                         uint32_t b0, uint32_t b1) {
    asm volatile(
        "mma.sync.aligned.m16n8k8.row.col.f32.tf32.tf32.f32 "
        "{%0,%1,%2,%3}, {%4,%5,%6,%7}, {%8,%9}, {%0,%1,%2,%3};"
        : "+f"(c[0]), "+f"(c[1]), "+f"(c[2]), "+f"(c[3])
        : "r"(a0), "r"(a1), "r"(a2), "r"(a3), "r"(b0), "r"(b1));
}

// ---------------- init / A precompute + structure check ----------------
__global__ void flag_init_kernel() { g_flag = 1; }

__global__ void neg_exp_kernel(const float* __restrict__ A_log, float* __restrict__ A, int n) {
    int i = blockIdx.x * blockDim.x + threadIdx.x;
    if (i < n) {
        float v = -__expf(A_log[i]);
        A[i] = v;
        int s = i & (DSTATE - 1);
        float expect = -(float)(s + 1);
        if (fabsf(v - expect) > 1e-3f * (float)(s + 1))
            atomicAnd(&g_flag, 0);
    }
}

// ================= tf32x3 tensor-core GEMM (cp.async 3-stage) =================
#define SA 20
#define SB 72
#define STG_FLOATS 3712
#define GEMM_SMEM_BYTES (3 * STG_FLOATS * 4)   // 44544

__global__ void __launch_bounds__(256, 2)
gemm_tf32(const float* __restrict__ A, int lda,
          const float* __restrict__ B, int ldb,
          const float* __restrict__ bias,
          float* __restrict__ C, int ldc, size_t cstride,
          int N, int Klen, int act)
{
    extern __shared__ float sm[];
    const int tid  = threadIdx.x;
    const int row0 = blockIdx.y * 128;
    const int col0 = blockIdx.x * 64;

    const int kbase = blockIdx.z * Klen;
    A += kbase;
    B += (size_t)kbase * ldb;
    C += (size_t)blockIdx.z * cstride;

    const uint32_t smb = smem_u32(sm);

    const int a_r = tid >> 2;
    const int a_q = (tid & 3) << 2;
    const int b_k = tid >> 4;
    const int b_q = (tid & 15) << 2;
    const int b_bytes = (col0 + b_q + 4 <= N) ? 16 : 0;

    const int lane = tid & 31;
    const int rin  = lane >> 2;
    const int cin  = lane & 3;
    const int wid  = tid >> 5;
    const int warp_m = (wid & 3) * 32;
    const int warp_n = (wid >> 2) * 32;

    float acc[2][4][4];
#pragma unroll
    for (int mt = 0; mt < 2; mt++)
#pragma unroll
        for (int nt = 0; nt < 4; nt++)
#pragma unroll
            for (int i = 0; i < 4; i++) acc[mt][nt][i] = 0.0f;

    const int nk = Klen >> 4;

    auto issue = [&](int kc) {
        int slot = kc % 3;
        uint32_t ab = smb + slot * (STG_FLOATS * 4);
        uint32_t bb = ab + 2560 * 4;
        int k0 = kc << 4;
        cp16(ab + (a_r * SA + a_q) * 4,
             A + (size_t)(row0 + a_r) * lda + k0 + a_q, 16);
        cp16(ab + ((a_r + 64) * SA + a_q) * 4,
             A + (size_t)(row0 + a_r + 64) * lda + k0 + a_q, 16);
        const float* bs = B + (size_t)(k0 + b_k) * ldb + col0 + b_q;
        cp16(bb + (b_k * SB + b_q) * 4, b_bytes ? bs : B, b_bytes);
    };

    issue(0); CP_COMMIT();
    if (nk > 1) issue(1);
    CP_COMMIT();

    for (int kc = 0; kc < nk; kc++) {
        CP_WAIT1();
        __syncthreads();

        const float* as = sm + (kc % 3) * STG_FLOATS;
        const float* bs = as + 2560;

#pragma unroll
        for (int ks = 0; ks < 2; ks++) {
            int k8 = ks * 8;
            float ar[2][4], br[4][2];
#pragma unroll
            for (int mt = 0; mt < 2; mt++) {
                int mb = warp_m + mt * 16 + rin;
                ar[mt][0] = as[mb * SA + k8 + cin];
                ar[mt][1] = as[(mb + 8) * SA + k8 + cin];
                ar[mt][2] = as[mb * SA + k8 + cin + 4];
                ar[mt][3] = as[(mb + 8) * SA + k8 + cin + 4];
            }
#pragma unroll
            for (int nt = 0; nt < 4; nt++) {
                int nb = warp_n + nt * 8 + rin;
                br[nt][0] = bs[(k8 + cin) * SB + nb];
                br[nt][1] = bs[(k8 + cin + 4) * SB + nb];
            }
            uint32_t Ah[2][4], Al[2][4], Bh[4][2], Bl[4][2];
#pragma unroll
            for (int mt = 0; mt < 2; mt++)
#pragma unroll
                for (int j = 0; j < 4; j++) {
                    float h = tf32r(ar[mt][j]);
                    Ah[mt][j] = __float_as_uint(h);
                    Al[mt][j] = __float_as_uint(tf32r(ar[mt][j] - h));
                }
#pragma unroll
            for (int nt = 0; nt < 4; nt++)
#pragma unroll
                for (int j = 0; j < 2; j++) {
                    float h = tf32r(br[nt][j]);
                    Bh[nt][j] = __float_as_uint(h);
                    Bl[nt][j] = __float_as_uint(tf32r(br[nt][j] - h));
                }
#pragma unroll
            for (int mt = 0; mt < 2; mt++)
#pragma unroll
                for (int nt = 0; nt < 4; nt++) {
                    mma_tf32(acc[mt][nt], Ah[mt][0], Ah[mt][1], Ah[mt][2], Ah[mt][3],
                             Bh[nt][0], Bh[nt][1]);
                    mma_tf32(acc[mt][nt], Al[mt][0], Al[mt][1], Al[mt][2], Al[mt][3],
                             Bh[nt][0], Bh[nt][1]);
                    mma_tf32(acc[mt][nt], Ah[mt][0], Ah[mt][1], Ah[mt][2], Ah[mt][3],
                             Bl[nt][0], Bl[nt][1]);
                }
        }

        if (kc + 2 < nk) issue(kc + 2);
        CP_COMMIT();
    }

#pragma unroll
    for (int mt = 0; mt < 2; mt++) {
#pragma unroll
        for (int nt = 0; nt < 4; nt++) {
            int rg = row0 + warp_m + mt * 16 + rin;
            int cg = col0 + warp_n + nt * 8 + cin * 2;
            if (cg >= N) continue;
            float v0 = acc[mt][nt][0], v1 = acc[mt][nt][1];
            float v2 = acc[mt][nt][2], v3 = acc[mt][nt][3];
            if (act == 1) {
                float b0 = bias[cg], b1 = bias[cg + 1];
                v0 = softplus_f(v0 + b0); v1 = softplus_f(v1 + b1);
                v2 = softplus_f(v2 + b0); v3 = softplus_f(v3 + b1);
            }
            *(float2*)(C + (size_t)rg * ldc + cg)       = make_float2(v0, v1);
            *(float2*)(C + (size_t)(rg + 8) * ldc + cg) = make_float2(v2, v3);
        }
    }
}

// ---------------- split-K reduce ----------------
__global__ void reduce_split(const float* __restrict__ part, float* __restrict__ outp, int n) {
    int i = blockIdx.x * blockDim.x + threadIdx.x;
    if (i >= n) return;
    float s = 0.0f;
#pragma unroll
    for (int k = 0; k < NSPLIT; k++) s += part[(size_t)k * n + i];
    outp[i] = s;
}

// ---------------- causal depthwise conv (width 4) + bias + silu, float4 ----------
__global__ void conv_silu_kernel(const float* __restrict__ xz,
                                 const float* __restrict__ conv_w,
                                 const float* __restrict__ conv_b,
                                 float* __restrict__ u_out)
{
    int q = blockIdx.x * blockDim.x + threadIdx.x;
    const int total4 = MTOT * DINNER / 4;
    if (q >= total4) return;
    int bl = q >> 9;               // / (DINNER/4)
    int j  = (q & 511) << 2;       // d offset (multiple of 4)
    int l  = bl & (LEN - 1);
    int b  = bl >> 10;

    const float* base = xz + (size_t)b * LEN * 2 * DINNER + j;
    float4 acc = *(const float4*)(conv_b + j);
    float4 cw0 = *(const float4*)(conv_w + (size_t)(j + 0) * DCONV);
    float4 cw1 = *(const float4*)(conv_w + (size_t)(j + 1) * DCONV);
    float4 cw2 = *(const float4*)(conv_w + (size_t)(j + 2) * DCONV);
    float4 cw3 = *(const float4*)(conv_w + (size_t)(j + 3) * DCONV);
    const float* w0 = (const float*)&cw0;
    const float* w1 = (const float*)&cw1;
    const float* w2 = (const float*)&cw2;
    const float* w3 = (const float*)&cw3;

#pragma unroll
    for (int kk = 0; kk < DCONV; kk++) {
        int ll = l + kk - (DCONV - 1);
        if (ll >= 0) {
            float4 xv = *(const float4*)(base + (size_t)ll * 2 * DINNER);
            acc.x = fmaf(xv.x, w0[kk], acc.x);
            acc.y = fmaf(xv.y, w1[kk], acc.y);
            acc.z = fmaf(xv.z, w2[kk], acc.z);
            acc.w = fmaf(xv.w, w3[kk], acc.w);
        }
    }
    float4 o;
    o.x = silu_f(acc.x); o.y = silu_f(acc.y);
    o.z = silu_f(acc.z); o.w = silu_f(acc.w);
    *(float4*)(u_out + (size_t)bl * DINNER + j) = o;
}

// ================= parallel selective scan (fast path, 3 passes) =================
// Pass 1 v3: ONE thread per channel, h[16] in registers, no shuffles.
// Grid (NCH/P1_C, NT). Coalesced direct gmem for delta/u/y/qcum; tiny smem BC tile.
__global__ void __launch_bounds__(256)
scan_pass1(const float* __restrict__ delta,
           const float* __restrict__ u,
           const float* __restrict__ xdbl,
           const float* __restrict__ Aneg,
           float* __restrict__ y_local,
           float* __restrict__ qcum_out,
           float* __restrict__ h_end,
           float* __restrict__ qc_tot,
           const int* __restrict__ flagp)
{
    if (!*flagp) return;

    __shared__ float sBC[2][32][32];

    const int tid = threadIdx.x;
    const int g   = blockIdx.x * P1_C;
    const int k   = blockIdx.y;
    const int b   = g >> 11;
    const int d   = (g & (DINNER - 1)) + tid;
    const size_t blbase = (size_t)b * LEN + (size_t)k * CHUNK_L;

    const float abase = Aneg[d * DSTATE];

    const float* dptr = delta + blbase * DINNER + d;
    const float* uptr = u     + blbase * DINNER + d;
    const float* bcb  = xdbl  + blbase * XDBL_N + DTRANK;
    float* yptr = y_local  + blbase * DINNER + d;
    float* qptr = qcum_out + blbase * DINNER + d;

    const int pr = tid >> 3;       // 0..31
    const int ps = (tid & 7) << 2; // 0..28
    const uint32_t aBC = smem_u32(sBC);

    auto prefetch = [&](int sub) {
        uint32_t off = (uint32_t)(((sub & 1) * 32 + pr) * 32 + ps) * 4;
        cp16(aBC + off, bcb + (size_t)(sub * 32 + pr) * XDBL_N + ps, 16);
        CP_COMMIT();
    };

    float h[DSTATE];
#pragma unroll
    for (int n = 0; n < DSTATE; n++) h[n] = 0.0f;
    float qc = 1.0f;

    prefetch(0);
    const int NS = CHUNK_L / 32;   // 2

    for (int sub = 0; sub < NS; sub++) {
        CP_WAIT0();
        __syncthreads();
        if (sub + 1 < NS) prefetch(sub + 1);
        const float (*bc)[32] = sBC[sub & 1];

#pragma unroll 2
        for (int l = 0; l < 32; l++) {
            size_t so = (size_t)(sub * 32 + l) * DINNER;
            float dl = dptr[so];
            float ul = uptr[so];
            float4 B0 = *(const float4*)&bc[l][0];
            float4 B1 = *(const float4*)&bc[l][4];
            float4 B2 = *(const float4*)&bc[l][8];
            float4 B3 = *(const float4*)&bc[l][12];
            float4 C0 = *(const float4*)&bc[l][16];
            float4 C1 = *(const float4*)&bc[l][20];
            float4 C2 = *(const float4*)&bc[l][24];
            float4 C3 = *(const float4*)&bc[l][28];

            float q  = __expf(dl * abase);
            float q2 = q * q, q4 = q2 * q2, q8 = q4 * q4;
            float du = dl * ul;

            float p3  = q2 * q;
            float p5  = q4 * q;
            float p6  = q4 * q2;
            float p7  = p6 * q;
            float p9  = q8 * q;
            float p10 = q8 * q2;
            float p11 = p10 * q;
            float p12 = q8 * q4;
            float p13 = p12 * q;
            float p14 = p12 * q2;
            float p15 = p14 * q;
            float p16 = q8 * q8;

            h[0]  = fmaf(q,   h[0],  du * B0.x);
            h[1]  = fmaf(q2,  h[1],  du * B0.y);
            h[2]  = fmaf(p3,  h[2],  du * B0.z);
            h[3]  = fmaf(q4,  h[3],  du * B0.w);
            h[4]  = fmaf(p5,  h[4],  du * B1.x);
            h[5]  = fmaf(p6,  h[5],  du * B1.y);
            h[6]  = fmaf(p7,  h[6],  du * B1.z);
            h[7]  = fmaf(q8,  h[7],  du * B1.w);
            h[8]  = fmaf(p9,  h[8],  du * B2.x);
            h[9]  = fmaf(p10, h[9],  du * B2.y);
            h[10] = fmaf(p11, h[10], du * B2.z);
            h[11] = fmaf(p12, h[11], du * B2.w);
            h[12] = fmaf(p13, h[12], du * B3.x);
            h[13] = fmaf(p14, h[13], du * B3.y);
            h[14] = fmaf(p15, h[14], du * B3.z);
            h[15] = fmaf(p16, h[15], du * B3.w);

            float ya = fmaf(h[0],  C0.x, h[1]  * C0.y);
            float yb = fmaf(h[2],  C0.z, h[3]  * C0.w);
            float yc = fmaf(h[4],  C1.x, h[5]  * C1.y);
            float yd = fmaf(h[6],  C1.z, h[7]  * C1.w);
            ya += fmaf(h[8],  C2.x, h[9]  * C2.y);
            yb += fmaf(h[10], C2.z, h[11] * C2.w);
            yc += fmaf(h[12], C3.x, h[13] * C3.y);
            yd += fmaf(h[14], C3.z, h[15] * C3.w);

            qc *= q;
            yptr[so] = (ya + yb) + (yc + yd);
            qptr[so] = qc;
        }
        __syncthreads();
    }

    const int bd = b * DINNER + d;
#pragma unroll
    for (int n = 0; n < DSTATE; n++)
        h_end[((size_t)k * DSTATE + n) * NCH + bd] = h[n];
    qc_tot[(size_t)k * NCH + bd] = qc;
}

// Pass 2: prefix over chunk carries. One thread per (n, bd).
__global__ void scan_pass2(const float* __restrict__ h_end,
                           const float* __restrict__ qc_tot,
                           float* __restrict__ h_start,
                           const int* __restrict__ flagp)
{
    if (!*flagp) return;
    int idx = blockIdx.x * blockDim.x + threadIdx.x;
    if (idx >= DSTATE * NCH) return;
    int n  = idx / NCH;
    int bd = idx - n * NCH;
    int e  = n + 1;

    float hs = 0.0f;
#pragma unroll
    for (int k = 0; k < NT; k++) {
        h_start[((size_t)k * DSTATE + n) * NCH + bd] = hs;
        float qc = qc_tot[(size_t)k * NCH + bd];
        float q2 = qc * qc, q4 = q2 * q2, q8 = q4 * q4, q16 = q8 * q8;
        float p = 1.0f;
        if (e & 1) p *= qc;
        if (e & 2) p *= q2;
        if (e & 4) p *= q4;
        if (e & 8) p *= q8;
        if (e & 16) p *= q16;
        hs = fmaf(p, hs, h_end[((size_t)k * DSTATE + n) * NCH + bd]);
    }
}

// Pass 3: elementwise correction + gating.
__global__ void __launch_bounds__(256)
scan_pass3(float* __restrict__ y,
           const float* __restrict__ qcum,
           const float* __restrict__ h_start,
           const float* __restrict__ xdbl,
           const float* __restrict__ u,
           const float* __restrict__ xz,
           const float* __restrict__ D_skip,
           const int* __restrict__ flagp)
{
    if (!*flagp) return;
    int idx = blockIdx.x * blockDim.x + threadIdx.x;
    if (idx >= MTOT * DINNER) return;
    int d  = idx & (DINNER - 1);
    int bl = idx >> 11;
    int l  = bl & (LEN - 1);
    int b  = bl >> 10;
    int k  = l >> CHUNK_SHIFT;
    int bd = b * DINNER + d;

    float q = qcum[idx];
    const float* Crow = xdbl + (size_t)bl * XDBL_N + DTRANK + DSTATE;
    const float* hs   = h_start + (size_t)k * DSTATE * NCH + bd;

    float acc = 0.0f;
    float pn = q;
#pragma unroll
    for (int n = 0; n < DSTATE; n++) {
        acc = fmaf(Crow[n] * hs[(size_t)n * NCH], pn, acc);
        pn *= q;
    }

    float ul = u[idx];
    float zl = xz[(size_t)bl * 2 * DINNER + DINNER + d];
    float yl = y[idx];
    y[idx] = (yl + acc + ul * D_skip[d]) * silu_f(zl);
}

// ---------------- monolithic fallback scan (generic A; runs only if !fast) ------
__global__ void __launch_bounds__(256)
scan_fallback(const float* __restrict__ delta,
              const float* __restrict__ u,
              const float* __restrict__ xdbl,
              const float* __restrict__ xz,
              const float* __restrict__ Aneg,
              const float* __restrict__ D_skip,
              float* __restrict__ y,
              const int* __restrict__ flagp)
{
    if (*flagp) return;
    int tid  = blockIdx.x * blockDim.x + threadIdx.x;
    int t    = tid & 7;
    int chan = tid >> 3;
    if (chan >= NCH) return;
    int b = chan / DINNER;
    int d = chan % DINNER;
    int n0 = t * 2;

    float a0 = Aneg[d * DSTATE + n0];
    float a1 = Aneg[d * DSTATE + n0 + 1];
    float dskip = D_skip[d];

    const float* dptr = delta + (size_t)b * LEN * DINNER + d;
    const float* uptr = u     + (size_t)b * LEN * DINNER + d;
    const float* xd   = xdbl  + (size_t)b * LEN * XDBL_N;
    const float* zptr = xz    + (size_t)b * LEN * 2 * DINNER + DINNER + d;
    float*       yptr = y     + (size_t)b * LEN * DINNER + d;

    float h0 = 0.0f, h1 = 0.0f;
#pragma unroll 2
    for (int l = 0; l < LEN; l++) {
        float dl = dptr[(size_t)l * DINNER];
        float ul = uptr[(size_t)l * DINNER];
        const float* xr = xd + (size_t)l * XDBL_N;
        float Bn0 = xr[DTRANK + n0];
        float Bn1 = xr[DTRANK + n0 + 1];
        float Cn0 = xr[DTRANK + DSTATE + n0];
        float Cn1 = xr[DTRANK + DSTATE + n0 + 1];

        float du = dl * ul;
        h0 = fmaf(__expf(dl * a0), h0, du * Bn0);
        h1 = fmaf(__expf(dl * a1), h1, du * Bn1);

        float part = fmaf(h0, Cn0, h1 * Cn1);
        part += __shfl_xor_sync(0xffffffffu, part, 1);
        part += __shfl_xor_sync(0xffffffffu, part, 2);
        part += __shfl_xor_sync(0xffffffffu, part, 4);

        if (t == 0) {
            float z = zptr[(size_t)l * 2 * DINNER];
            yptr[(size_t)l * DINNER] = (part + ul * dskip) * silu_f(z);
        }
    }
}

// ---------------- launcher ----------------
extern "C" void kernel_launch(void* const* d_in, const int* in_sizes, int n_in,
                              void* d_out, int out_size)
{
    const float* x      = (const float*)d_in[0];
    const float* W_in   = (const float*)d_in[1];
    const float* conv_w = (const float*)d_in[2];
    const float* conv_b = (const float*)d_in[3];
    const float* W_x    = (const float*)d_in[4];
    const float* W_dt   = (const float*)d_in[5];
    const float* b_dt   = (const float*)d_in[6];
    const float* A_log  = (const float*)d_in[7];
    const float* D_skip = (const float*)d_in[8];
    const float* W_out  = (const float*)d_in[9];
    float* out = (float*)d_out;

    float *xz, *u, *xdbl, *part, *delta, *y, *qcum, *hend, *hstart, *qct, *Aneg;
    int* flagp;
    cudaGetSymbolAddress((void**)&xz,     g_xz);
    cudaGetSymbolAddress((void**)&u,      g_u);
    cudaGetSymbolAddress((void**)&xdbl,   g_xdbl);
    cudaGetSymbolAddress((void**)&part,   g_part);
    cudaGetSymbolAddress((void**)&delta,  g_delta);
    cudaGetSymbolAddress((void**)&y,      g_y);
    cudaGetSymbolAddress((void**)&qcum,   g_qcum);
    cudaGetSymbolAddress((void**)&hend,   g_hend);
    cudaGetSymbolAddress((void**)&hstart, g_hstart);
    cudaGetSymbolAddress((void**)&qct,    g_qct);
    cudaGetSymbolAddress((void**)&Aneg,   g_Aneg);
    cudaGetSymbolAddress((void**)&flagp,  g_flag);

    static bool attr_set = false;
    if (!attr_set) {
        cudaFuncSetAttribute(gemm_tf32, cudaFuncAttributeMaxDynamicSharedMemorySize,
                             GEMM_SMEM_BYTES);
        attr_set = true;
    }

    flag_init_kernel<<<1, 1>>>();
    neg_exp_kernel<<<(DINNER * DSTATE + 255) / 256, 256>>>(A_log, Aneg, DINNER * DSTATE);

    // 1) xz = x @ W_in   [2048 x 4096], K=1024
    gemm_tf32<<<dim3(4096 / 64, MTOT / 128), 256, GEMM_SMEM_BYTES>>>(
        x, DMODEL, W_in, 2 * DINNER, nullptr, xz, 2 * DINNER, 0,
        2 * DINNER, DMODEL, 0);

    // 2) conv + silu -> u
    conv_silu_kernel<<<(MTOT * DINNER / 4 + 255) / 256, 256>>>(xz, conv_w, conv_b, u);

    // 3) x_dbl = u @ W_x   [2048 x 96], K=2048 via split-K=8 + reduce
    gemm_tf32<<<dim3(2, MTOT / 128, NSPLIT), 256, GEMM_SMEM_BYTES>>>(
        u, DINNER, W_x, XDBL_N, nullptr, part, XDBL_N, (size_t)MTOT * XDBL_N,
        XDBL_N, DINNER / NSPLIT, 0);
    reduce_split<<<(MTOT * XDBL_N + 255) / 256, 256>>>(part, xdbl, MTOT * XDBL_N);

    // 4) delta = softplus(dt @ W_dt + b_dt)   [2048 x 2048], K=64
    gemm_tf32<<<dim3(DINNER / 64, MTOT / 128), 256, GEMM_SMEM_BYTES>>>(
        xdbl, XDBL_N, W_dt, DINNER, b_dt, delta, DINNER, 0,
        DINNER, DTRANK, 1);

    // 5) selective scan: 3-pass parallel-in-time (fast) + monolithic fallback
    scan_pass1<<<dim3(NCH / P1_C, NT), 256>>>(delta, u, xdbl, Aneg, y, qcum,
                                              hend, qct, flagp);
    scan_pass2<<<(DSTATE * NCH + 255) / 256, 256>>>(hend, qct, hstart, flagp);
    scan_pass3<<<(MTOT * DINNER + 255) / 256, 256>>>(y, qcum, hstart, xdbl, u,
                                                     xz, D_skip, flagp);
    scan_fallback<<<(NCH * 8) / 256, 256>>>(delta, u, xdbl, xz, Aneg, D_skip, y, flagp);

    // 6) out = y @ W_out   [2048 x 1024], K=2048
    gemm_tf32<<<dim3(DMODEL / 64, MTOT / 128), 256, GEMM_SMEM_BYTES>>>(
        y, DINNER, W_out, DMODEL, nullptr, out, DMODEL, 0,
        DMODEL, DINNER, 0);
}

// round 9
// speedup vs baseline: 5.9985x; 1.3017x over previous
#include <cuda_runtime.h>
#include <cuda_bf16.h>
#include <math.h>
#include <cstdint>

// ---------------- problem constants ----------------
#define BATCH   2
#define LEN     1024
#define DMODEL  1024
#define DSTATE  16
#define DCONV   4
#define DINNER  2048
#define DTRANK  64
#define XDBL_N  (DTRANK + 2*DSTATE)   // 96
#define MTOT    (BATCH*LEN)           // 2048
#define NSPLIT  8
#define NT      16
#define CHUNK_L (LEN/NT)              // 64
#define CHUNK_SHIFT 6
#define NCH     (BATCH*DINNER)        // 4096
#define P1_C    256

// ---------------- scratch (device globals) ----------------
__device__ __align__(256) float g_xz   [(size_t)MTOT * 2 * DINNER];
__device__ __align__(256) float g_u    [(size_t)MTOT * DINNER];
__device__ __align__(256) float g_xdbl [(size_t)MTOT * XDBL_N];
__device__ __align__(256) float g_part [(size_t)NSPLIT * MTOT * XDBL_N];
__device__ __align__(256) float g_delta[(size_t)MTOT * DINNER];
__device__ __align__(256) float g_y    [(size_t)MTOT * DINNER];
__device__ __align__(256) float g_qcum [(size_t)MTOT * DINNER];
__device__ __align__(256) float g_hend [(size_t)NT * DSTATE * NCH];
__device__ __align__(256) float g_hstart[(size_t)NT * DSTATE * NCH];
__device__ __align__(256) float g_qct  [(size_t)NT * NCH];
__device__ __align__(256) float g_Aneg [DINNER * DSTATE];
__device__ int g_flag;

// bf16 hi/lo operand buffers
__device__ __align__(256) __nv_bfloat16 g_xh [(size_t)MTOT*DMODEL],  g_xl [(size_t)MTOT*DMODEL];
__device__ __align__(256) __nv_bfloat16 g_uh [(size_t)MTOT*DINNER],  g_ul [(size_t)MTOT*DINNER];
__device__ __align__(256) __nv_bfloat16 g_xdh[(size_t)MTOT*XDBL_N],  g_xdl[(size_t)MTOT*XDBL_N];
__device__ __align__(256) __nv_bfloat16 g_yh [(size_t)MTOT*DINNER],  g_yl [(size_t)MTOT*DINNER];
__device__ __align__(256) __nv_bfloat16 g_winT_h[(size_t)2*DINNER*DMODEL], g_winT_l[(size_t)2*DINNER*DMODEL];
__device__ __align__(256) __nv_bfloat16 g_wxT_h [(size_t)XDBL_N*DINNER],   g_wxT_l [(size_t)XDBL_N*DINNER];
__device__ __align__(256) __nv_bfloat16 g_wdtT_h[(size_t)DINNER*DTRANK],   g_wdtT_l[(size_t)DINNER*DTRANK];
__device__ __align__(256) __nv_bfloat16 g_woutT_h[(size_t)DMODEL*DINNER],  g_woutT_l[(size_t)DMODEL*DINNER];

// ---------------- helpers ----------------
__device__ __forceinline__ float silu_f(float x)     { return x / (1.0f + __expf(-x)); }
__device__ __forceinline__ float softplus_f(float x) { return fmaxf(x, 0.0f) + log1pf(expf(-fabsf(x))); }
__device__ __forceinline__ void split_bf16(float v, __nv_bfloat16& h, __nv_bfloat16& l) {
    h = __float2bfloat16(v);
    l = __float2bfloat16(v - __bfloat162float(h));
}
__device__ __forceinline__ uint32_t smem_u32(const void* p) {
    uint32_t a;
    asm("{ .reg .u64 t; cvta.to.shared.u64 t, %1; cvt.u32.u64 %0, t; }" : "=r"(a) : "l"(p));
    return a;
}
__device__ __forceinline__ void cp16(uint32_t dst, const void* src, int bytes) {
    asm volatile("cp.async.cg.shared.global [%0], [%1], 16, %2;"
                 :: "r"(dst), "l"(src), "r"(bytes));
}
#define CP_COMMIT() asm volatile("cp.async.commit_group;")
#define CP_WAIT1()  asm volatile("cp.async.wait_group 1;")
#define CP_WAIT0()  asm volatile("cp.async.wait_group 0;")

__device__ __forceinline__ void mma_bf16(float c[4], const uint32_t a[4], const uint32_t b[2]) {
    asm volatile(
        "mma.sync.aligned.m16n8k16.row.col.f32.bf16.bf16.f32 "
        "{%0,%1,%2,%3}, {%4,%5,%6,%7}, {%8,%9}, {%0,%1,%2,%3};"
        : "+f"(c[0]), "+f"(c[1]), "+f"(c[2]), "+f"(c[3])
        : "r"(a[0]), "r"(a[1]), "r"(a[2]), "r"(a[3]), "r"(b[0]), "r"(b[1]));
}

// ---------------- init / A precompute + structure check ----------------
__global__ void flag_init_kernel() { g_flag = 1; }

__global__ void neg_exp_kernel(const float* __restrict__ A_log, float* __restrict__ A, int n) {
    int i = blockIdx.x * blockDim.x + threadIdx.x;
    if (i < n) {
        float v = -__expf(A_log[i]);
        A[i] = v;
        int s = i & (DSTATE - 1);
        float expect = -(float)(s + 1);
        if (fabsf(v - expect) > 1e-3f * (float)(s + 1))
            atomicAnd(&g_flag, 0);
    }
}

// ---------------- prep: fp32 -> bf16 hi/lo (row-major, float4) ----------------
__global__ void cvt_hl(const float* __restrict__ in,
                       __nv_bfloat16* __restrict__ H, __nv_bfloat16* __restrict__ L,
                       int total4) {
    int q = blockIdx.x * blockDim.x + threadIdx.x;
    if (q >= total4) return;
    float4 v = *(const float4*)(in + (size_t)q * 4);
    __nv_bfloat16 h0, h1, h2, h3, l0, l1, l2, l3;
    split_bf16(v.x, h0, l0); split_bf16(v.y, h1, l1);
    split_bf16(v.z, h2, l2); split_bf16(v.w, h3, l3);
    __nv_bfloat162* Hp = (__nv_bfloat162*)(H + (size_t)q * 4);
    __nv_bfloat162* Lp = (__nv_bfloat162*)(L + (size_t)q * 4);
    Hp[0] = __nv_bfloat162(h0, h1); Hp[1] = __nv_bfloat162(h2, h3);
    Lp[0] = __nv_bfloat162(l0, l1); Lp[1] = __nv_bfloat162(l2, l3);
}

// ---------------- prep: fp32 [R][C] -> transposed bf16 hi/lo [C][R] ----------------
__global__ void tconv(const float* __restrict__ in, int ldin,
                      __nv_bfloat16* __restrict__ H, __nv_bfloat16* __restrict__ L, int R) {
    __shared__ float t[32][33];
    int c0 = blockIdx.x * 32, r0 = blockIdx.y * 32;
    int tx = threadIdx.x, ty = threadIdx.y;
#pragma unroll
    for (int i = 0; i < 4; i++)
        t[ty + i * 8][tx] = in[(size_t)(r0 + ty + i * 8) * ldin + c0 + tx];
    __syncthreads();
#pragma unroll
    for (int i = 0; i < 4; i++) {
        int oc = c0 + ty + i * 8;
        float v = t[tx][ty + i * 8];
        __nv_bfloat16 h, l;
        split_bf16(v, h, l);
        H[(size_t)oc * R + r0 + tx] = h;
        L[(size_t)oc * R + r0 + tx] = l;
    }
}

// ================= bf16x3 tensor-core GEMM (cp.async 3-stage) =================
// C[M,N] = A[M,K] @ B^T, A hi/lo row-major bf16, B stored transposed [N][K] hi/lo bf16.
// Block 128x64, KC=16, 256 thr (8 warps 4x2), warp tile 32x32.
// Smem per stage (uint32): AH 128x12, AL 128x12, BH 64x12, BL 64x12 = 4608 (18432 B)
#define STAGE_U32 4608
#define AH_U32 0
#define AL_U32 1536
#define BH_U32 3072
#define BL_U32 3840
#define GEMM_SMEM_BYTES (3 * STAGE_U32 * 4)   // 55296

__global__ void __launch_bounds__(256, 2)
gemm_bf16(const __nv_bfloat16* __restrict__ Ah, const __nv_bfloat16* __restrict__ Al, int lda,
          const __nv_bfloat16* __restrict__ Bh, const __nv_bfloat16* __restrict__ Bl, int ldb,
          const float* __restrict__ bias,
          float* __restrict__ C, int ldc, size_t cstride,
          int N, int Klen, int act)
{
    extern __shared__ uint32_t smu[];
    const int tid  = threadIdx.x;
    const int row0 = blockIdx.y * 128;
    const int col0 = blockIdx.x * 64;

    const int kbase = blockIdx.z * Klen;
    Ah += kbase; Al += kbase;
    Bh += kbase; Bl += kbase;
    C += (size_t)blockIdx.z * cstride;

    const uint32_t smb = smem_u32(smu);

    // copy maps: A 128 rows x 2 segs (16B each); B 64 rows x 2 segs, hi for tid<128
    const int a_r = tid >> 1;
    const int a_s = (tid & 1) << 3;        // bf16 offset 0 or 8
    const int b_r = (tid & 127) >> 1;
    const int b_s = (tid & 1) << 3;
    const bool b_hi = tid < 128;
    const int b_bytes = (col0 + b_r < N) ? 16 : 0;
    const __nv_bfloat16* Bsel = b_hi ? Bh : Bl;
    const uint32_t b_dst_u32 = (b_hi ? BH_U32 : BL_U32) + b_r * 12 + (b_s >> 1);

    // compute maps
    const int lane = tid & 31;
    const int g    = lane >> 2;
    const int tg   = lane & 3;
    const int wid  = tid >> 5;
    const int warp_m = (wid & 3) * 32;
    const int warp_n = (wid >> 2) * 32;

    float acc[2][4][4];
#pragma unroll
    for (int mt = 0; mt < 2; mt++)
#pragma unroll
        for (int nt = 0; nt < 4; nt++)
#pragma unroll
            for (int i = 0; i < 4; i++) acc[mt][nt][i] = 0.0f;

    const int nk = Klen >> 4;

    auto issue = [&](int kc) {
        uint32_t base = smb + (kc % 3) * (STAGE_U32 * 4);
        int k0 = kc << 4;
        cp16(base + (AH_U32 + a_r * 12 + (a_s >> 1)) * 4,
             Ah + (size_t)(row0 + a_r) * lda + k0 + a_s, 16);
        cp16(base + (AL_U32 + a_r * 12 + (a_s >> 1)) * 4,
             Al + (size_t)(row0 + a_r) * lda + k0 + a_s, 16);
        const __nv_bfloat16* bp = Bsel + (size_t)(col0 + b_r) * ldb + k0 + b_s;
        cp16(base + b_dst_u32 * 4, b_bytes ? bp : Bh, b_bytes);
    };

    issue(0); CP_COMMIT();
    if (nk > 1) issue(1);
    CP_COMMIT();

    for (int kc = 0; kc < nk; kc++) {
        CP_WAIT1();
        __syncthreads();

        const uint32_t* st = smu + (kc % 3) * STAGE_U32;
        const uint32_t* aH = st + AH_U32;
        const uint32_t* aL = st + AL_U32;
        const uint32_t* bH = st + BH_U32;
        const uint32_t* bL = st + BL_U32;

        uint32_t Afh[2][4], Afl[2][4], Bfh[4][2], Bfl[4][2];
#pragma unroll
        for (int mt = 0; mt < 2; mt++) {
            int r = warp_m + mt * 16 + g;
            Afh[mt][0] = aH[r * 12 + tg];
            Afh[mt][1] = aH[(r + 8) * 12 + tg];
            Afh[mt][2] = aH[r * 12 + tg + 4];
            Afh[mt][3] = aH[(r + 8) * 12 + tg + 4];
            Afl[mt][0] = aL[r * 12 + tg];
            Afl[mt][1] = aL[(r + 8) * 12 + tg];
            Afl[mt][2] = aL[r * 12 + tg + 4];
            Afl[mt][3] = aL[(r + 8) * 12 + tg + 4];
        }
#pragma unroll
        for (int nt = 0; nt < 4; nt++) {
            int rn = warp_n + nt * 8 + g;
            Bfh[nt][0] = bH[rn * 12 + tg];
            Bfh[nt][1] = bH[rn * 12 + tg + 4];
            Bfl[nt][0] = bL[rn * 12 + tg];
            Bfl[nt][1] = bL[rn * 12 + tg + 4];
        }
#pragma unroll
        for (int mt = 0; mt < 2; mt++)
#pragma unroll
            for (int nt = 0; nt < 4; nt++) {
                mma_bf16(acc[mt][nt], Afh[mt], Bfh[nt]);
                mma_bf16(acc[mt][nt], Afl[mt], Bfh[nt]);
                mma_bf16(acc[mt][nt], Afh[mt], Bfl[nt]);
            }

        if (kc + 2 < nk) issue(kc + 2);
        CP_COMMIT();
    }

    // ---- epilogue ----
#pragma unroll
    for (int mt = 0; mt < 2; mt++) {
#pragma unroll
        for (int nt = 0; nt < 4; nt++) {
            int rg = row0 + warp_m + mt * 16 + g;
            int cg = col0 + warp_n + nt * 8 + tg * 2;
            if (cg >= N) continue;
            float v0 = acc[mt][nt][0], v1 = acc[mt][nt][1];
            float v2 = acc[mt][nt][2], v3 = acc[mt][nt][3];
            if (act == 1) {
                float b0 = bias[cg], b1 = bias[cg + 1];
                v0 = softplus_f(v0 + b0); v1 = softplus_f(v1 + b1);
                v2 = softplus_f(v2 + b0); v3 = softplus_f(v3 + b1);
            }
            *(float2*)(C + (size_t)rg * ldc + cg)       = make_float2(v0, v1);
            *(float2*)(C + (size_t)(rg + 8) * ldc + cg) = make_float2(v2, v3);
        }
    }
}

// ---------------- split-K reduce + fused hi/lo convert ----------------
__global__ void reduce_split(const float* __restrict__ part, float* __restrict__ outp,
                             __nv_bfloat16* __restrict__ H, __nv_bfloat16* __restrict__ L,
                             int n) {
    int i = blockIdx.x * blockDim.x + threadIdx.x;
    if (i >= n) return;
    float s = 0.0f;
#pragma unroll
    for (int k = 0; k < NSPLIT; k++) s += part[(size_t)k * n + i];
    outp[i] = s;
    __nv_bfloat16 h, l;
    split_bf16(s, h, l);
    H[i] = h; L[i] = l;
}

// ---------------- conv (width 4) + bias + silu + fused hi/lo ----------------
__global__ void conv_silu_kernel(const float* __restrict__ xz,
                                 const float* __restrict__ conv_w,
                                 const float* __restrict__ conv_b,
                                 float* __restrict__ u_out,
                                 __nv_bfloat16* __restrict__ uh,
                                 __nv_bfloat16* __restrict__ ul)
{
    int q = blockIdx.x * blockDim.x + threadIdx.x;
    const int total4 = MTOT * DINNER / 4;
    if (q >= total4) return;
    int bl = q >> 9;
    int j  = (q & 511) << 2;
    int l  = bl & (LEN - 1);
    int b  = bl >> 10;

    const float* base = xz + (size_t)b * LEN * 2 * DINNER + j;
    float4 acc = *(const float4*)(conv_b + j);
    float4 cw0 = *(const float4*)(conv_w + (size_t)(j + 0) * DCONV);
    float4 cw1 = *(const float4*)(conv_w + (size_t)(j + 1) * DCONV);
    float4 cw2 = *(const float4*)(conv_w + (size_t)(j + 2) * DCONV);
    float4 cw3 = *(const float4*)(conv_w + (size_t)(j + 3) * DCONV);
    const float* w0 = (const float*)&cw0;
    const float* w1 = (const float*)&cw1;
    const float* w2 = (const float*)&cw2;
    const float* w3 = (const float*)&cw3;

#pragma unroll
    for (int kk = 0; kk < DCONV; kk++) {
        int ll = l + kk - (DCONV - 1);
        if (ll >= 0) {
            float4 xv = *(const float4*)(base + (size_t)ll * 2 * DINNER);
            acc.x = fmaf(xv.x, w0[kk], acc.x);
            acc.y = fmaf(xv.y, w1[kk], acc.y);
            acc.z = fmaf(xv.z, w2[kk], acc.z);
            acc.w = fmaf(xv.w, w3[kk], acc.w);
        }
    }
    float4 o;
    o.x = silu_f(acc.x); o.y = silu_f(acc.y);
    o.z = silu_f(acc.z); o.w = silu_f(acc.w);
    *(float4*)(u_out + (size_t)bl * DINNER + j) = o;

    __nv_bfloat16 h0, h1, h2, h3, l0, l1, l2, l3;
    split_bf16(o.x, h0, l0); split_bf16(o.y, h1, l1);
    split_bf16(o.z, h2, l2); split_bf16(o.w, h3, l3);
    __nv_bfloat162* Hp = (__nv_bfloat162*)(uh + (size_t)bl * DINNER + j);
    __nv_bfloat162* Lp = (__nv_bfloat162*)(ul + (size_t)bl * DINNER + j);
    Hp[0] = __nv_bfloat162(h0, h1); Hp[1] = __nv_bfloat162(h2, h3);
    Lp[0] = __nv_bfloat162(l0, l1); Lp[1] = __nv_bfloat162(l2, l3);
}

// ================= parallel selective scan (fast path, 3 passes) =================
__global__ void __launch_bounds__(256)
scan_pass1(const float* __restrict__ delta,
           const float* __restrict__ u,
           const float* __restrict__ xdbl,
           const float* __restrict__ Aneg,
           float* __restrict__ y_local,
           float* __restrict__ qcum_out,
           float* __restrict__ h_end,
           float* __restrict__ qc_tot,
           const int* __restrict__ flagp)
{
    if (!*flagp) return;

    __shared__ float sBC[2][32][32];

    const int tid = threadIdx.x;
    const int g   = blockIdx.x * P1_C;
    const int k   = blockIdx.y;
    const int b   = g >> 11;
    const int d   = (g & (DINNER - 1)) + tid;
    const size_t blbase = (size_t)b * LEN + (size_t)k * CHUNK_L;

    const float abase = Aneg[d * DSTATE];

    const float* dptr = delta + blbase * DINNER + d;
    const float* uptr = u     + blbase * DINNER + d;
    const float* bcb  = xdbl  + blbase * XDBL_N + DTRANK;
    float* yptr = y_local  + blbase * DINNER + d;
    float* qptr = qcum_out + blbase * DINNER + d;

    const int pr = tid >> 3;
    const int ps = (tid & 7) << 2;
    const uint32_t aBC = smem_u32(sBC);

    auto prefetch = [&](int sub) {
        uint32_t off = (uint32_t)(((sub & 1) * 32 + pr) * 32 + ps) * 4;
        cp16(aBC + off, bcb + (size_t)(sub * 32 + pr) * XDBL_N + ps, 16);
        CP_COMMIT();
    };

    float h[DSTATE];
#pragma unroll
    for (int n = 0; n < DSTATE; n++) h[n] = 0.0f;
    float qc = 1.0f;

    prefetch(0);
    const int NS = CHUNK_L / 32;

    for (int sub = 0; sub < NS; sub++) {
        CP_WAIT0();
        __syncthreads();
        if (sub + 1 < NS) prefetch(sub + 1);
        const float (*bc)[32] = sBC[sub & 1];

#pragma unroll 2
        for (int l = 0; l < 32; l++) {
            size_t so = (size_t)(sub * 32 + l) * DINNER;
            float dl = dptr[so];
            float ul = uptr[so];
            float4 B0 = *(const float4*)&bc[l][0];
            float4 B1 = *(const float4*)&bc[l][4];
            float4 B2 = *(const float4*)&bc[l][8];
            float4 B3 = *(const float4*)&bc[l][12];
            float4 C0 = *(const float4*)&bc[l][16];
            float4 C1 = *(const float4*)&bc[l][20];
            float4 C2 = *(const float4*)&bc[l][24];
            float4 C3 = *(const float4*)&bc[l][28];

            float q  = __expf(dl * abase);
            float q2 = q * q, q4 = q2 * q2, q8 = q4 * q4;
            float du = dl * ul;

            float p3  = q2 * q;
            float p5  = q4 * q;
            float p6  = q4 * q2;
            float p7  = p6 * q;
            float p9  = q8 * q;
            float p10 = q8 * q2;
            float p11 = p10 * q;
            float p12 = q8 * q4;
            float p13 = p12 * q;
            float p14 = p12 * q2;
            float p15 = p14 * q;
            float p16 = q8 * q8;

            h[0]  = fmaf(q,   h[0],  du * B0.x);
            h[1]  = fmaf(q2,  h[1],  du * B0.y);
            h[2]  = fmaf(p3,  h[2],  du * B0.z);
            h[3]  = fmaf(q4,  h[3],  du * B0.w);
            h[4]  = fmaf(p5,  h[4],  du * B1.x);
            h[5]  = fmaf(p6,  h[5],  du * B1.y);
            h[6]  = fmaf(p7,  h[6],  du * B1.z);
            h[7]  = fmaf(q8,  h[7],  du * B1.w);
            h[8]  = fmaf(p9,  h[8],  du * B2.x);
            h[9]  = fmaf(p10, h[9],  du * B2.y);
            h[10] = fmaf(p11, h[10], du * B2.z);
            h[11] = fmaf(p12, h[11], du * B2.w);
            h[12] = fmaf(p13, h[12], du * B3.x);
            h[13] = fmaf(p14, h[13], du * B3.y);
            h[14] = fmaf(p15, h[14], du * B3.z);
            h[15] = fmaf(p16, h[15], du * B3.w);

            float ya = fmaf(h[0],  C0.x, h[1]  * C0.y);
            float yb = fmaf(h[2],  C0.z, h[3]  * C0.w);
            float yc = fmaf(h[4],  C1.x, h[5]  * C1.y);
            float yd = fmaf(h[6],  C1.z, h[7]  * C1.w);
            ya += fmaf(h[8],  C2.x, h[9]  * C2.y);
            yb += fmaf(h[10], C2.z, h[11] * C2.w);
            yc += fmaf(h[12], C3.x, h[13] * C3.y);
            yd += fmaf(h[14], C3.z, h[15] * C3.w);

            qc *= q;
            yptr[so] = (ya + yb) + (yc + yd);
            qptr[so] = qc;
        }
        __syncthreads();
    }

    const int bd = b * DINNER + d;
#pragma unroll
    for (int n = 0; n < DSTATE; n++)
        h_end[((size_t)k * DSTATE + n) * NCH + bd] = h[n];
    qc_tot[(size_t)k * NCH + bd] = qc;
}

__global__ void scan_pass2(const float* __restrict__ h_end,
                           const float* __restrict__ qc_tot,
                           float* __restrict__ h_start,
                           const int* __restrict__ flagp)
{
    if (!*flagp) return;
    int idx = blockIdx.x * blockDim.x + threadIdx.x;
    if (idx >= DSTATE * NCH) return;
    int n  = idx / NCH;
    int bd = idx - n * NCH;
    int e  = n + 1;

    float hs = 0.0f;
#pragma unroll
    for (int k = 0; k < NT; k++) {
        h_start[((size_t)k * DSTATE + n) * NCH + bd] = hs;
        float qc = qc_tot[(size_t)k * NCH + bd];
        float q2 = qc * qc, q4 = q2 * q2, q8 = q4 * q4, q16 = q8 * q8;
        float p = 1.0f;
        if (e & 1) p *= qc;
        if (e & 2) p *= q2;
        if (e & 4) p *= q4;
        if (e & 8) p *= q8;
        if (e & 16) p *= q16;
        hs = fmaf(p, hs, h_end[((size_t)k * DSTATE + n) * NCH + bd]);
    }
}

// Pass 3: correction + gating + fused hi/lo convert of y
__global__ void __launch_bounds__(256)
scan_pass3(float* __restrict__ y,
           const float* __restrict__ qcum,
           const float* __restrict__ h_start,
           const float* __restrict__ xdbl,
           const float* __restrict__ u,
           const float* __restrict__ xz,
           const float* __restrict__ D_skip,
           __nv_bfloat16* __restrict__ yh,
           __nv_bfloat16* __restrict__ yl,
           const int* __restrict__ flagp)
{
    if (!*flagp) return;
    int idx = blockIdx.x * blockDim.x + threadIdx.x;
    if (idx >= MTOT * DINNER) return;
    int d  = idx & (DINNER - 1);
    int bl = idx >> 11;
    int l  = bl & (LEN - 1);
    int b  = bl >> 10;
    int k  = l >> CHUNK_SHIFT;
    int bd = b * DINNER + d;

    float q = qcum[idx];
    const float* Crow = xdbl + (size_t)bl * XDBL_N + DTRANK + DSTATE;
    const float* hs   = h_start + (size_t)k * DSTATE * NCH + bd;

    float acc = 0.0f;
    float pn = q;
#pragma unroll
    for (int n = 0; n < DSTATE; n++) {
        acc = fmaf(Crow[n] * hs[(size_t)n * NCH], pn, acc);
        pn *= q;
    }

    float ul = u[idx];
    float zl = xz[(size_t)bl * 2 * DINNER + DINNER + d];
    float yl_ = y[idx];
    float v = (yl_ + acc + ul * D_skip[d]) * silu_f(zl);
    y[idx] = v;
    __nv_bfloat16 h, lo;
    split_bf16(v, h, lo);
    yh[idx] = h; yl[idx] = lo;
}

// ---------------- fallback scan (generic A) + guarded y convert ----------------
__global__ void __launch_bounds__(256)
scan_fallback(const float* __restrict__ delta,
              const float* __restrict__ u,
              const float* __restrict__ xdbl,
              const float* __restrict__ xz,
              const float* __restrict__ Aneg,
              const float* __restrict__ D_skip,
              float* __restrict__ y,
              const int* __restrict__ flagp)
{
    if (*flagp) return;
    int tid  = blockIdx.x * blockDim.x + threadIdx.x;
    int t    = tid & 7;
    int chan = tid >> 3;
    if (chan >= NCH) return;
    int b = chan / DINNER;
    int d = chan % DINNER;
    int n0 = t * 2;

    float a0 = Aneg[d * DSTATE + n0];
    float a1 = Aneg[d * DSTATE + n0 + 1];
    float dskip = D_skip[d];

    const float* dptr = delta + (size_t)b * LEN * DINNER + d;
    const float* uptr = u     + (size_t)b * LEN * DINNER + d;
    const float* xd   = xdbl  + (size_t)b * LEN * XDBL_N;
    const float* zptr = xz    + (size_t)b * LEN * 2 * DINNER + DINNER + d;
    float*       yptr = y     + (size_t)b * LEN * DINNER + d;

    float h0 = 0.0f, h1 = 0.0f;
#pragma unroll 2
    for (int l = 0; l < LEN; l++) {
        float dl = dptr[(size_t)l * DINNER];
        float ul = uptr[(size_t)l * DINNER];
        const float* xr = xd + (size_t)l * XDBL_N;
        float Bn0 = xr[DTRANK + n0];
        float Bn1 = xr[DTRANK + n0 + 1];
        float Cn0 = xr[DTRANK + DSTATE + n0];
        float Cn1 = xr[DTRANK + DSTATE + n0 + 1];

        float du = dl * ul;
        h0 = fmaf(__expf(dl * a0), h0, du * Bn0);
        h1 = fmaf(__expf(dl * a1), h1, du * Bn1);

        float part = fmaf(h0, Cn0, h1 * Cn1);
        part += __shfl_xor_sync(0xffffffffu, part, 1);
        part += __shfl_xor_sync(0xffffffffu, part, 2);
        part += __shfl_xor_sync(0xffffffffu, part, 4);

        if (t == 0) {
            float z = zptr[(size_t)l * 2 * DINNER];
            yptr[(size_t)l * DINNER] = (part + ul * dskip) * silu_f(z);
        }
    }
}

__global__ void cvt_y_fallback(const float* __restrict__ y,
                               __nv_bfloat16* __restrict__ H, __nv_bfloat16* __restrict__ L,
                               const int* __restrict__ flagp) {
    if (*flagp) return;
    int i = blockIdx.x * blockDim.x + threadIdx.x;
    if (i >= MTOT * DINNER) return;
    __nv_bfloat16 h, l;
    split_bf16(y[i], h, l);
    H[i] = h; L[i] = l;
}

// ---------------- launcher ----------------
extern "C" void kernel_launch(void* const* d_in, const int* in_sizes, int n_in,
                              void* d_out, int out_size)
{
    const float* x      = (const float*)d_in[0];
    const float* W_in   = (const float*)d_in[1];
    const float* conv_w = (const float*)d_in[2];
    const float* conv_b = (const float*)d_in[3];
    const float* W_x    = (const float*)d_in[4];
    const float* W_dt   = (const float*)d_in[5];
    const float* b_dt   = (const float*)d_in[6];
    const float* A_log  = (const float*)d_in[7];
    const float* D_skip = (const float*)d_in[8];
    const float* W_out  = (const float*)d_in[9];
    float* out = (float*)d_out;

    float *xz, *u, *xdbl, *part, *delta, *y, *qcum, *hend, *hstart, *qct, *Aneg;
    int* flagp;
    cudaGetSymbolAddress((void**)&xz,     g_xz);
    cudaGetSymbolAddress((void**)&u,      g_u);
    cudaGetSymbolAddress((void**)&xdbl,   g_xdbl);
    cudaGetSymbolAddress((void**)&part,   g_part);
    cudaGetSymbolAddress((void**)&delta,  g_delta);
    cudaGetSymbolAddress((void**)&y,      g_y);
    cudaGetSymbolAddress((void**)&qcum,   g_qcum);
    cudaGetSymbolAddress((void**)&hend,   g_hend);
    cudaGetSymbolAddress((void**)&hstart, g_hstart);
    cudaGetSymbolAddress((void**)&qct,    g_qct);
    cudaGetSymbolAddress((void**)&Aneg,   g_Aneg);
    cudaGetSymbolAddress((void**)&flagp,  g_flag);

    __nv_bfloat16 *xh,*xl,*uh,*ul,*xdh,*xdl,*yh,*yl;
    __nv_bfloat16 *winTh,*winTl,*wxTh,*wxTl,*wdtTh,*wdtTl,*woTh,*woTl;
    cudaGetSymbolAddress((void**)&xh,  g_xh);   cudaGetSymbolAddress((void**)&xl,  g_xl);
    cudaGetSymbolAddress((void**)&uh,  g_uh);   cudaGetSymbolAddress((void**)&ul,  g_ul);
    cudaGetSymbolAddress((void**)&xdh, g_xdh);  cudaGetSymbolAddress((void**)&xdl, g_xdl);
    cudaGetSymbolAddress((void**)&yh,  g_yh);   cudaGetSymbolAddress((void**)&yl,  g_yl);
    cudaGetSymbolAddress((void**)&winTh, g_winT_h);  cudaGetSymbolAddress((void**)&winTl, g_winT_l);
    cudaGetSymbolAddress((void**)&wxTh,  g_wxT_h);   cudaGetSymbolAddress((void**)&wxTl,  g_wxT_l);
    cudaGetSymbolAddress((void**)&wdtTh, g_wdtT_h);  cudaGetSymbolAddress((void**)&wdtTl, g_wdtT_l);
    cudaGetSymbolAddress((void**)&woTh,  g_woutT_h); cudaGetSymbolAddress((void**)&woTl,  g_woutT_l);

    static bool attr_set = false;
    if (!attr_set) {
        cudaFuncSetAttribute(gemm_bf16, cudaFuncAttributeMaxDynamicSharedMemorySize,
                             GEMM_SMEM_BYTES);
        attr_set = true;
    }

    dim3 tb(32, 8);

    flag_init_kernel<<<1, 1>>>();
    neg_exp_kernel<<<(DINNER * DSTATE + 255) / 256, 256>>>(A_log, Aneg, DINNER * DSTATE);

    // prep: x hi/lo; transposed weights hi/lo
    cvt_hl<<<(MTOT * DMODEL / 4 + 255) / 256, 256>>>(x, xh, xl, MTOT * DMODEL / 4);
    tconv<<<dim3(2 * DINNER / 32, DMODEL / 32), tb>>>(W_in, 2 * DINNER, winTh, winTl, DMODEL);
    tconv<<<dim3(XDBL_N / 32, DINNER / 32), tb>>>(W_x, XDBL_N, wxTh, wxTl, DINNER);
    tconv<<<dim3(DINNER / 32, DTRANK / 32), tb>>>(W_dt, DINNER, wdtTh, wdtTl, DTRANK);
    tconv<<<dim3(DMODEL / 32, DINNER / 32), tb>>>(W_out, DMODEL, woTh, woTl, DINNER);

    // 1) xz = x @ W_in   [2048 x 4096], K=1024
    gemm_bf16<<<dim3(4096 / 64, MTOT / 128), 256, GEMM_SMEM_BYTES>>>(
        xh, xl, DMODEL, winTh, winTl, DMODEL, nullptr, xz, 2 * DINNER, 0,
        2 * DINNER, DMODEL, 0);

    // 2) conv + silu -> u (+ hi/lo)
    conv_silu_kernel<<<(MTOT * DINNER / 4 + 255) / 256, 256>>>(xz, conv_w, conv_b, u, uh, ul);

    // 3) x_dbl = u @ W_x   [2048 x 96], K=2048 via split-K=8 + reduce (+ hi/lo)
    gemm_bf16<<<dim3(2, MTOT / 128, NSPLIT), 256, GEMM_SMEM_BYTES>>>(
        uh, ul, DINNER, wxTh, wxTl, DINNER, nullptr, part, XDBL_N, (size_t)MTOT * XDBL_N,
        XDBL_N, DINNER / NSPLIT, 0);
    reduce_split<<<(MTOT * XDBL_N + 255) / 256, 256>>>(part, xdbl, xdh, xdl, MTOT * XDBL_N);

    // 4) delta = softplus(dt @ W_dt + b_dt)   [2048 x 2048], K=64
    gemm_bf16<<<dim3(DINNER / 64, MTOT / 128), 256, GEMM_SMEM_BYTES>>>(
        xdh, xdl, XDBL_N, wdtTh, wdtTl, DTRANK, b_dt, delta, DINNER, 0,
        DINNER, DTRANK, 1);

    // 5) scan: 3-pass parallel-in-time (fast) + fallback
    scan_pass1<<<dim3(NCH / P1_C, NT), 256>>>(delta, u, xdbl, Aneg, y, qcum,
                                              hend, qct, flagp);
    scan_pass2<<<(DSTATE * NCH + 255) / 256, 256>>>(hend, qct, hstart, flagp);
    scan_pass3<<<(MTOT * DINNER + 255) / 256, 256>>>(y, qcum, hstart, xdbl, u,
                                                     xz, D_skip, yh, yl, flagp);
    scan_fallback<<<(NCH * 8) / 256, 256>>>(delta, u, xdbl, xz, Aneg, D_skip, y, flagp);
    cvt_y_fallback<<<(MTOT * DINNER + 255) / 256, 256>>>(y, yh, yl, flagp);

    // 6) out = y @ W_out   [2048 x 1024], K=2048
    gemm_bf16<<<dim3(DMODEL / 64, MTOT / 128), 256, GEMM_SMEM_BYTES>>>(
        yh, yl, DINNER, woTh, woTl, DINNER, nullptr, out, DMODEL, 0,
        DMODEL, DINNER, 0);
}

// round 10
// speedup vs baseline: 6.5902x; 1.0986x over previous
#include <cuda_runtime.h>
#include <cuda_bf16.h>
#include <math.h>
#include <cstdint>

// ---------------- problem constants ----------------
#define BATCH   2
#define LEN     1024
#define DMODEL  1024
#define DSTATE  16
#define DCONV   4
#define DINNER  2048
#define DTRANK  64
#define XDBL_N  (DTRANK + 2*DSTATE)   // 96
#define MTOT    (BATCH*LEN)           // 2048
#define NSPLIT  8
#define NT      16
#define CHUNK_L (LEN/NT)              // 64
#define CHUNK_SHIFT 6
#define NCH     (BATCH*DINNER)        // 4096
#define P1_C    256

// ---------------- scratch (device globals) ----------------
__device__ __align__(256) float g_xz   [(size_t)MTOT * 2 * DINNER];
__device__ __align__(256) float g_u    [(size_t)MTOT * DINNER];
__device__ __align__(256) float g_xdbl [(size_t)MTOT * XDBL_N];
__device__ __align__(256) float g_part [(size_t)NSPLIT * MTOT * XDBL_N];
__device__ __align__(256) float g_delta[(size_t)MTOT * DINNER];
__device__ __align__(256) float g_y    [(size_t)MTOT * DINNER];
__device__ __align__(256) float g_qcum [(size_t)MTOT * DINNER];
__device__ __align__(256) float g_hend [(size_t)NT * DSTATE * NCH];
__device__ __align__(256) float g_hstart[(size_t)NT * DSTATE * NCH];
__device__ __align__(256) float g_qct  [(size_t)NT * NCH];
__device__ __align__(256) float g_Aneg [DINNER * DSTATE];
__device__ int g_flag;

// bf16 hi/lo operand buffers
__device__ __align__(256) __nv_bfloat16 g_xh [(size_t)MTOT*DMODEL],  g_xl [(size_t)MTOT*DMODEL];
__device__ __align__(256) __nv_bfloat16 g_uh [(size_t)MTOT*DINNER],  g_ul [(size_t)MTOT*DINNER];
__device__ __align__(256) __nv_bfloat16 g_xdh[(size_t)MTOT*XDBL_N],  g_xdl[(size_t)MTOT*XDBL_N];
__device__ __align__(256) __nv_bfloat16 g_yh [(size_t)MTOT*DINNER],  g_yl [(size_t)MTOT*DINNER];
__device__ __align__(256) __nv_bfloat16 g_winT_h[(size_t)2*DINNER*DMODEL], g_winT_l[(size_t)2*DINNER*DMODEL];
__device__ __align__(256) __nv_bfloat16 g_wxT_h [(size_t)XDBL_N*DINNER],   g_wxT_l [(size_t)XDBL_N*DINNER];
__device__ __align__(256) __nv_bfloat16 g_wdtT_h[(size_t)DINNER*DTRANK],   g_wdtT_l[(size_t)DINNER*DTRANK];
__device__ __align__(256) __nv_bfloat16 g_woutT_h[(size_t)DMODEL*DINNER],  g_woutT_l[(size_t)DMODEL*DINNER];

// ---------------- helpers ----------------
__device__ __forceinline__ float silu_f(float x)     { return x / (1.0f + __expf(-x)); }
__device__ __forceinline__ float softplus_f(float x) { return fmaxf(x, 0.0f) + log1pf(expf(-fabsf(x))); }
__device__ __forceinline__ void split_bf16(float v, __nv_bfloat16& h, __nv_bfloat16& l) {
    h = __float2bfloat16(v);
    l = __float2bfloat16(v - __bfloat162float(h));
}
__device__ __forceinline__ uint32_t smem_u32(const void* p) {
    uint32_t a;
    asm("{ .reg .u64 t; cvta.to.shared.u64 t, %1; cvt.u32.u64 %0, t; }" : "=r"(a) : "l"(p));
    return a;
}
__device__ __forceinline__ void cp16(uint32_t dst, const void* src, int bytes) {
    asm volatile("cp.async.cg.shared.global [%0], [%1], 16, %2;"
                 :: "r"(dst), "l"(src), "r"(bytes));
}
#define CP_COMMIT() asm volatile("cp.async.commit_group;")
#define CP_WAIT1()  asm volatile("cp.async.wait_group 1;")
#define CP_WAIT0()  asm volatile("cp.async.wait_group 0;")

#define LDSM_X4(r, addr) \
    asm volatile("ldmatrix.sync.aligned.m8n8.x4.shared.b16 {%0,%1,%2,%3}, [%4];" \
                 : "=r"((r)[0]), "=r"((r)[1]), "=r"((r)[2]), "=r"((r)[3]) : "r"(addr))

__device__ __forceinline__ void mma_bf16(float c[4], const uint32_t a[4], const uint32_t b[2]) {
    asm volatile(
        "mma.sync.aligned.m16n8k16.row.col.f32.bf16.bf16.f32 "
        "{%0,%1,%2,%3}, {%4,%5,%6,%7}, {%8,%9}, {%0,%1,%2,%3};"
        : "+f"(c[0]), "+f"(c[1]), "+f"(c[2]), "+f"(c[3])
        : "r"(a[0]), "r"(a[1]), "r"(a[2]), "r"(a[3]), "r"(b[0]), "r"(b[1]));
}

// ---------------- init / A precompute + structure check ----------------
__global__ void flag_init_kernel() { g_flag = 1; }

__global__ void neg_exp_kernel(const float* __restrict__ A_log, float* __restrict__ A, int n) {
    int i = blockIdx.x * blockDim.x + threadIdx.x;
    if (i < n) {
        float v = -__expf(A_log[i]);
        A[i] = v;
        int s = i & (DSTATE - 1);
        float expect = -(float)(s + 1);
        if (fabsf(v - expect) > 1e-3f * (float)(s + 1))
            atomicAnd(&g_flag, 0);
    }
}

// ---------------- prep: fp32 -> bf16 hi/lo (row-major, float4) ----------------
__global__ void cvt_hl(const float* __restrict__ in,
                       __nv_bfloat16* __restrict__ H, __nv_bfloat16* __restrict__ L,
                       int total4) {
    int q = blockIdx.x * blockDim.x + threadIdx.x;
    if (q >= total4) return;
    float4 v = *(const float4*)(in + (size_t)q * 4);
    __nv_bfloat16 h0, h1, h2, h3, l0, l1, l2, l3;
    split_bf16(v.x, h0, l0); split_bf16(v.y, h1, l1);
    split_bf16(v.z, h2, l2); split_bf16(v.w, h3, l3);
    __nv_bfloat162* Hp = (__nv_bfloat162*)(H + (size_t)q * 4);
    __nv_bfloat162* Lp = (__nv_bfloat162*)(L + (size_t)q * 4);
    Hp[0] = __nv_bfloat162(h0, h1); Hp[1] = __nv_bfloat162(h2, h3);
    Lp[0] = __nv_bfloat162(l0, l1); Lp[1] = __nv_bfloat162(l2, l3);
}

// ---------------- prep: fp32 [R][C] -> transposed bf16 hi/lo [C][R] ----------------
__global__ void tconv(const float* __restrict__ in, int ldin,
                      __nv_bfloat16* __restrict__ H, __nv_bfloat16* __restrict__ L, int R) {
    __shared__ float t[32][33];
    int c0 = blockIdx.x * 32, r0 = blockIdx.y * 32;
    int tx = threadIdx.x, ty = threadIdx.y;
#pragma unroll
    for (int i = 0; i < 4; i++)
        t[ty + i * 8][tx] = in[(size_t)(r0 + ty + i * 8) * ldin + c0 + tx];
    __syncthreads();
#pragma unroll
    for (int i = 0; i < 4; i++) {
        int oc = c0 + ty + i * 8;
        float v = t[tx][ty + i * 8];
        __nv_bfloat16 h, l;
        split_bf16(v, h, l);
        H[(size_t)oc * R + r0 + tx] = h;
        L[(size_t)oc * R + r0 + tx] = l;
    }
}

// ================= bf16x3 tensor-core GEMM (cp.async 3-stage, ldmatrix) =================
// C[M,N] = A[M,K] @ B^T, A hi/lo row-major bf16, B stored transposed [N][K] hi/lo bf16.
// Block 128x64, KC=16, 256 thr (8 warps 4x2), warp tile 32x32.
// Smem per stage (uint32): AH 128x12, AL 128x12, BH 64x12, BL 64x12 = 4608 (18432 B)
#define STAGE_U32 4608
#define AH_U32 0
#define AL_U32 1536
#define BH_U32 3072
#define BL_U32 3840
#define GEMM_SMEM_BYTES (3 * STAGE_U32 * 4)   // 55296

__global__ void __launch_bounds__(256, 2)
gemm_bf16(const __nv_bfloat16* __restrict__ Ah, const __nv_bfloat16* __restrict__ Al, int lda,
          const __nv_bfloat16* __restrict__ Bh, const __nv_bfloat16* __restrict__ Bl, int ldb,
          const float* __restrict__ bias,
          float* __restrict__ C, int ldc, size_t cstride,
          int N, int Klen, int act)
{
    extern __shared__ uint32_t smu[];
    const int tid  = threadIdx.x;
    const int row0 = blockIdx.y * 128;
    const int col0 = blockIdx.x * 64;

    const int kbase = blockIdx.z * Klen;
    Ah += kbase; Al += kbase;
    Bh += kbase; Bl += kbase;
    C += (size_t)blockIdx.z * cstride;

    const uint32_t smb = smem_u32(smu);

    // copy maps
    const int a_r = tid >> 1;
    const int a_s = (tid & 1) << 3;
    const int b_r = (tid & 127) >> 1;
    const int b_s = (tid & 1) << 3;
    const bool b_hi = tid < 128;
    const int b_bytes = (col0 + b_r < N) ? 16 : 0;
    const __nv_bfloat16* Bsel = b_hi ? Bh : Bl;
    const uint32_t b_dst_u32 = (b_hi ? BH_U32 : BL_U32) + b_r * 12 + (b_s >> 1);

    // compute maps
    const int lane = tid & 31;
    const int g    = lane >> 2;
    const int tg   = lane & 3;
    const int wid  = tid >> 5;
    const int warp_m = (wid & 3) * 32;
    const int warp_n = (wid >> 2) * 32;

    // ldmatrix lane-address components (u32 units within a stage)
    const uint32_t aoff = (uint32_t)(warp_m + (lane & 15)) * 12 + (uint32_t)(lane >> 4) * 4;
    const uint32_t boff = (uint32_t)(warp_n + ((lane >> 4) << 3) + (lane & 7)) * 12
                        + (uint32_t)((lane >> 3) & 1) * 4;

    float acc[2][4][4];
#pragma unroll
    for (int mt = 0; mt < 2; mt++)
#pragma unroll
        for (int nt = 0; nt < 4; nt++)
#pragma unroll
            for (int i = 0; i < 4; i++) acc[mt][nt][i] = 0.0f;

    const int nk = Klen >> 4;

    auto issue = [&](int kc) {
        uint32_t base = smb + (kc % 3) * (STAGE_U32 * 4);
        int k0 = kc << 4;
        cp16(base + (AH_U32 + a_r * 12 + (a_s >> 1)) * 4,
             Ah + (size_t)(row0 + a_r) * lda + k0 + a_s, 16);
        cp16(base + (AL_U32 + a_r * 12 + (a_s >> 1)) * 4,
             Al + (size_t)(row0 + a_r) * lda + k0 + a_s, 16);
        const __nv_bfloat16* bp = Bsel + (size_t)(col0 + b_r) * ldb + k0 + b_s;
        cp16(base + b_dst_u32 * 4, b_bytes ? bp : Bh, b_bytes);
    };

    issue(0); CP_COMMIT();
    if (nk > 1) issue(1);
    CP_COMMIT();

    for (int kc = 0; kc < nk; kc++) {
        CP_WAIT1();
        __syncthreads();

        uint32_t stg = smb + (kc % 3) * (STAGE_U32 * 4);

        uint32_t Afh[2][4], Afl[2][4], Bfh[8], Bfl[8];
        LDSM_X4(Afh[0], stg + (AH_U32 + aoff) * 4);
        LDSM_X4(Afh[1], stg + (AH_U32 + aoff + 192) * 4);   // +16 rows
        LDSM_X4(Afl[0], stg + (AL_U32 + aoff) * 4);
        LDSM_X4(Afl[1], stg + (AL_U32 + aoff + 192) * 4);
        LDSM_X4(Bfh,     stg + (BH_U32 + boff) * 4);
        LDSM_X4(Bfh + 4, stg + (BH_U32 + boff + 192) * 4);  // +16 n-rows
        LDSM_X4(Bfl,     stg + (BL_U32 + boff) * 4);
        LDSM_X4(Bfl + 4, stg + (BL_U32 + boff + 192) * 4);

#pragma unroll
        for (int mt = 0; mt < 2; mt++)
#pragma unroll
            for (int nt = 0; nt < 4; nt++) {
                mma_bf16(acc[mt][nt], Afh[mt], Bfh + nt * 2);
                mma_bf16(acc[mt][nt], Afl[mt], Bfh + nt * 2);
                mma_bf16(acc[mt][nt], Afh[mt], Bfl + nt * 2);
            }

        if (kc + 2 < nk) issue(kc + 2);
        CP_COMMIT();
    }

    // ---- epilogue ----
#pragma unroll
    for (int mt = 0; mt < 2; mt++) {
#pragma unroll
        for (int nt = 0; nt < 4; nt++) {
            int rg = row0 + warp_m + mt * 16 + g;
            int cg = col0 + warp_n + nt * 8 + tg * 2;
            if (cg >= N) continue;
            float v0 = acc[mt][nt][0], v1 = acc[mt][nt][1];
            float v2 = acc[mt][nt][2], v3 = acc[mt][nt][3];
            if (act == 1) {
                float b0 = bias[cg], b1 = bias[cg + 1];
                v0 = softplus_f(v0 + b0); v1 = softplus_f(v1 + b1);
                v2 = softplus_f(v2 + b0); v3 = softplus_f(v3 + b1);
            }
            *(float2*)(C + (size_t)rg * ldc + cg)       = make_float2(v0, v1);
            *(float2*)(C + (size_t)(rg + 8) * ldc + cg) = make_float2(v2, v3);
        }
    }
}

// ---------------- split-K reduce + fused hi/lo convert ----------------
__global__ void reduce_split(const float* __restrict__ part, float* __restrict__ outp,
                             __nv_bfloat16* __restrict__ H, __nv_bfloat16* __restrict__ L,
                             int n) {
    int i = blockIdx.x * blockDim.x + threadIdx.x;
    if (i >= n) return;
    float s = 0.0f;
#pragma unroll
    for (int k = 0; k < NSPLIT; k++) s += part[(size_t)k * n + i];
    outp[i] = s;
    __nv_bfloat16 h, l;
    split_bf16(s, h, l);
    H[i] = h; L[i] = l;
}

// ---------------- conv (width 4) + bias + silu + fused hi/lo ----------------
__global__ void conv_silu_kernel(const float* __restrict__ xz,
                                 const float* __restrict__ conv_w,
                                 const float* __restrict__ conv_b,
                                 float* __restrict__ u_out,
                                 __nv_bfloat16* __restrict__ uh,
                                 __nv_bfloat16* __restrict__ ul)
{
    int q = blockIdx.x * blockDim.x + threadIdx.x;
    const int total4 = MTOT * DINNER / 4;
    if (q >= total4) return;
    int bl = q >> 9;
    int j  = (q & 511) << 2;
    int l  = bl & (LEN - 1);
    int b  = bl >> 10;

    const float* base = xz + (size_t)b * LEN * 2 * DINNER + j;
    float4 acc = *(const float4*)(conv_b + j);
    float4 cw0 = *(const float4*)(conv_w + (size_t)(j + 0) * DCONV);
    float4 cw1 = *(const float4*)(conv_w + (size_t)(j + 1) * DCONV);
    float4 cw2 = *(const float4*)(conv_w + (size_t)(j + 2) * DCONV);
    float4 cw3 = *(const float4*)(conv_w + (size_t)(j + 3) * DCONV);
    const float* w0 = (const float*)&cw0;
    const float* w1 = (const float*)&cw1;
    const float* w2 = (const float*)&cw2;
    const float* w3 = (const float*)&cw3;

#pragma unroll
    for (int kk = 0; kk < DCONV; kk++) {
        int ll = l + kk - (DCONV - 1);
        if (ll >= 0) {
            float4 xv = *(const float4*)(base + (size_t)ll * 2 * DINNER);
            acc.x = fmaf(xv.x, w0[kk], acc.x);
            acc.y = fmaf(xv.y, w1[kk], acc.y);
            acc.z = fmaf(xv.z, w2[kk], acc.z);
            acc.w = fmaf(xv.w, w3[kk], acc.w);
        }
    }
    float4 o;
    o.x = silu_f(acc.x); o.y = silu_f(acc.y);
    o.z = silu_f(acc.z); o.w = silu_f(acc.w);
    *(float4*)(u_out + (size_t)bl * DINNER + j) = o;

    __nv_bfloat16 h0, h1, h2, h3, l0, l1, l2, l3;
    split_bf16(o.x, h0, l0); split_bf16(o.y, h1, l1);
    split_bf16(o.z, h2, l2); split_bf16(o.w, h3, l3);
    __nv_bfloat162* Hp = (__nv_bfloat162*)(uh + (size_t)bl * DINNER + j);
    __nv_bfloat162* Lp = (__nv_bfloat162*)(ul + (size_t)bl * DINNER + j);
    Hp[0] = __nv_bfloat162(h0, h1); Hp[1] = __nv_bfloat162(h2, h3);
    Lp[0] = __nv_bfloat162(l0, l1); Lp[1] = __nv_bfloat162(l2, l3);
}

// ================= parallel selective scan (fast path, 3 passes) =================
__global__ void __launch_bounds__(256)
scan_pass1(const float* __restrict__ delta,
           const float* __restrict__ u,
           const float* __restrict__ xdbl,
           const float* __restrict__ Aneg,
           float* __restrict__ y_local,
           float* __restrict__ qcum_out,
           float* __restrict__ h_end,
           float* __restrict__ qc_tot,
           const int* __restrict__ flagp)
{
    if (!*flagp) return;

    __shared__ float sBC[2][32][32];

    const int tid = threadIdx.x;
    const int g   = blockIdx.x * P1_C;
    const int k   = blockIdx.y;
    const int b   = g >> 11;
    const int d   = (g & (DINNER - 1)) + tid;
    const size_t blbase = (size_t)b * LEN + (size_t)k * CHUNK_L;

    const float abase = Aneg[d * DSTATE];

    const float* dptr = delta + blbase * DINNER + d;
    const float* uptr = u     + blbase * DINNER + d;
    const float* bcb  = xdbl  + blbase * XDBL_N + DTRANK;
    float* yptr = y_local  + blbase * DINNER + d;
    float* qptr = qcum_out + blbase * DINNER + d;

    const int pr = tid >> 3;
    const int ps = (tid & 7) << 2;
    const uint32_t aBC = smem_u32(sBC);

    auto prefetch = [&](int sub) {
        uint32_t off = (uint32_t)(((sub & 1) * 32 + pr) * 32 + ps) * 4;
        cp16(aBC + off, bcb + (size_t)(sub * 32 + pr) * XDBL_N + ps, 16);
        CP_COMMIT();
    };

    float h[DSTATE];
#pragma unroll
    for (int n = 0; n < DSTATE; n++) h[n] = 0.0f;
    float qc = 1.0f;

    prefetch(0);
    const int NS = CHUNK_L / 32;

    for (int sub = 0; sub < NS; sub++) {
        CP_WAIT0();
        __syncthreads();
        if (sub + 1 < NS) prefetch(sub + 1);
        const float (*bc)[32] = sBC[sub & 1];

#pragma unroll 2
        for (int l = 0; l < 32; l++) {
            size_t so = (size_t)(sub * 32 + l) * DINNER;
            float dl = dptr[so];
            float ul = uptr[so];
            float4 B0 = *(const float4*)&bc[l][0];
            float4 B1 = *(const float4*)&bc[l][4];
            float4 B2 = *(const float4*)&bc[l][8];
            float4 B3 = *(const float4*)&bc[l][12];
            float4 C0 = *(const float4*)&bc[l][16];
            float4 C1 = *(const float4*)&bc[l][20];
            float4 C2 = *(const float4*)&bc[l][24];
            float4 C3 = *(const float4*)&bc[l][28];

            float q  = __expf(dl * abase);
            float q2 = q * q, q4 = q2 * q2, q8 = q4 * q4;
            float du = dl * ul;

            float p3  = q2 * q;
            float p5  = q4 * q;
            float p6  = q4 * q2;
            float p7  = p6 * q;
            float p9  = q8 * q;
            float p10 = q8 * q2;
            float p11 = p10 * q;
            float p12 = q8 * q4;
            float p13 = p12 * q;
            float p14 = p12 * q2;
            float p15 = p14 * q;
            float p16 = q8 * q8;

            h[0]  = fmaf(q,   h[0],  du * B0.x);
            h[1]  = fmaf(q2,  h[1],  du * B0.y);
            h[2]  = fmaf(p3,  h[2],  du * B0.z);
            h[3]  = fmaf(q4,  h[3],  du * B0.w);
            h[4]  = fmaf(p5,  h[4],  du * B1.x);
            h[5]  = fmaf(p6,  h[5],  du * B1.y);
            h[6]  = fmaf(p7,  h[6],  du * B1.z);
            h[7]  = fmaf(q8,  h[7],  du * B1.w);
            h[8]  = fmaf(p9,  h[8],  du * B2.x);
            h[9]  = fmaf(p10, h[9],  du * B2.y);
            h[10] = fmaf(p11, h[10], du * B2.z);
            h[11] = fmaf(p12, h[11], du * B2.w);
            h[12] = fmaf(p13, h[12], du * B3.x);
            h[13] = fmaf(p14, h[13], du * B3.y);
            h[14] = fmaf(p15, h[14], du * B3.z);
            h[15] = fmaf(p16, h[15], du * B3.w);

            float ya = fmaf(h[0],  C0.x, h[1]  * C0.y);
            float yb = fmaf(h[2],  C0.z, h[3]  * C0.w);
            float yc = fmaf(h[4],  C1.x, h[5]  * C1.y);
            float yd = fmaf(h[6],  C1.z, h[7]  * C1.w);
            ya += fmaf(h[8],  C2.x, h[9]  * C2.y);
            yb += fmaf(h[10], C2.z, h[11] * C2.w);
            yc += fmaf(h[12], C3.x, h[13] * C3.y);
            yd += fmaf(h[14], C3.z, h[15] * C3.w);

            qc *= q;
            yptr[so] = (ya + yb) + (yc + yd);
            qptr[so] = qc;
        }
        __syncthreads();
    }

    const int bd = b * DINNER + d;
#pragma unroll
    for (int n = 0; n < DSTATE; n++)
        h_end[((size_t)k * DSTATE + n) * NCH + bd] = h[n];
    qc_tot[(size_t)k * NCH + bd] = qc;
}

__global__ void scan_pass2(const float* __restrict__ h_end,
                           const float* __restrict__ qc_tot,
                           float* __restrict__ h_start,
                           const int* __restrict__ flagp)
{
    if (!*flagp) return;
    int idx = blockIdx.x * blockDim.x + threadIdx.x;
    if (idx >= DSTATE * NCH) return;
    int n  = idx / NCH;
    int bd = idx - n * NCH;
    int e  = n + 1;

    float hs = 0.0f;
#pragma unroll
    for (int k = 0; k < NT; k++) {
        h_start[((size_t)k * DSTATE + n) * NCH + bd] = hs;
        float qc = qc_tot[(size_t)k * NCH + bd];
        float q2 = qc * qc, q4 = q2 * q2, q8 = q4 * q4, q16 = q8 * q8;
        float p = 1.0f;
        if (e & 1) p *= qc;
        if (e & 2) p *= q2;
        if (e & 4) p *= q4;
        if (e & 8) p *= q8;
        if (e & 16) p *= q16;
        hs = fmaf(p, hs, h_end[((size_t)k * DSTATE + n) * NCH + bd]);
    }
}

// Pass 3: correction + gating + fused hi/lo convert of y
__global__ void __launch_bounds__(256)
scan_pass3(float* __restrict__ y,
           const float* __restrict__ qcum,
           const float* __restrict__ h_start,
           const float* __restrict__ xdbl,
           const float* __restrict__ u,
           const float* __restrict__ xz,
           const float* __restrict__ D_skip,
           __nv_bfloat16* __restrict__ yh,
           __nv_bfloat16* __restrict__ yl,
           const int* __restrict__ flagp)
{
    if (!*flagp) return;
    int idx = blockIdx.x * blockDim.x + threadIdx.x;
    if (idx >= MTOT * DINNER) return;
    int d  = idx & (DINNER - 1);
    int bl = idx >> 11;
    int l  = bl & (LEN - 1);
    int b  = bl >> 10;
    int k  = l >> CHUNK_SHIFT;
    int bd = b * DINNER + d;

    float q = qcum[idx];
    const float* Crow = xdbl + (size_t)bl * XDBL_N + DTRANK + DSTATE;
    const float* hs   = h_start + (size_t)k * DSTATE * NCH + bd;

    float acc = 0.0f;
    float pn = q;
#pragma unroll
    for (int n = 0; n < DSTATE; n++) {
        acc = fmaf(Crow[n] * hs[(size_t)n * NCH], pn, acc);
        pn *= q;
    }

    float ul = u[idx];
    float zl = xz[(size_t)bl * 2 * DINNER + DINNER + d];
    float yl_ = y[idx];
    float v = (yl_ + acc + ul * D_skip[d]) * silu_f(zl);
    y[idx] = v;
    __nv_bfloat16 h, lo;
    split_bf16(v, h, lo);
    yh[idx] = h; yl[idx] = lo;
}

// ---------------- fallback scan (generic A) + guarded y convert ----------------
__global__ void __launch_bounds__(256)
scan_fallback(const float* __restrict__ delta,
              const float* __restrict__ u,
              const float* __restrict__ xdbl,
              const float* __restrict__ xz,
              const float* __restrict__ Aneg,
              const float* __restrict__ D_skip,
              float* __restrict__ y,
              const int* __restrict__ flagp)
{
    if (*flagp) return;
    int tid  = blockIdx.x * blockDim.x + threadIdx.x;
    int t    = tid & 7;
    int chan = tid >> 3;
    if (chan >= NCH) return;
    int b = chan / DINNER;
    int d = chan % DINNER;
    int n0 = t * 2;

    float a0 = Aneg[d * DSTATE + n0];
    float a1 = Aneg[d * DSTATE + n0 + 1];
    float dskip = D_skip[d];

    const float* dptr = delta + (size_t)b * LEN * DINNER + d;
    const float* uptr = u     + (size_t)b * LEN * DINNER + d;
    const float* xd   = xdbl  + (size_t)b * LEN * XDBL_N;
    const float* zptr = xz    + (size_t)b * LEN * 2 * DINNER + DINNER + d;
    float*       yptr = y     + (size_t)b * LEN * DINNER + d;

    float h0 = 0.0f, h1 = 0.0f;
#pragma unroll 2
    for (int l = 0; l < LEN; l++) {
        float dl = dptr[(size_t)l * DINNER];
        float ul = uptr[(size_t)l * DINNER];
        const float* xr = xd + (size_t)l * XDBL_N;
        float Bn0 = xr[DTRANK + n0];
        float Bn1 = xr[DTRANK + n0 + 1];
        float Cn0 = xr[DTRANK + DSTATE + n0];
        float Cn1 = xr[DTRANK + DSTATE + n0 + 1];

        float du = dl * ul;
        h0 = fmaf(__expf(dl * a0), h0, du * Bn0);
        h1 = fmaf(__expf(dl * a1), h1, du * Bn1);

        float part = fmaf(h0, Cn0, h1 * Cn1);
        part += __shfl_xor_sync(0xffffffffu, part, 1);
        part += __shfl_xor_sync(0xffffffffu, part, 2);
        part += __shfl_xor_sync(0xffffffffu, part, 4);

        if (t == 0) {
            float z = zptr[(size_t)l * 2 * DINNER];
            yptr[(size_t)l * DINNER] = (part + ul * dskip) * silu_f(z);
        }
    }
}

__global__ void cvt_y_fallback(const float* __restrict__ y,
                               __nv_bfloat16* __restrict__ H, __nv_bfloat16* __restrict__ L,
                               const int* __restrict__ flagp) {
    if (*flagp) return;
    int i = blockIdx.x * blockDim.x + threadIdx.x;
    if (i >= MTOT * DINNER) return;
    __nv_bfloat16 h, l;
    split_bf16(y[i], h, l);
    H[i] = h; L[i] = l;
}

// ---------------- launcher ----------------
extern "C" void kernel_launch(void* const* d_in, const int* in_sizes, int n_in,
                              void* d_out, int out_size)
{
    const float* x      = (const float*)d_in[0];
    const float* W_in   = (const float*)d_in[1];
    const float* conv_w = (const float*)d_in[2];
    const float* conv_b = (const float*)d_in[3];
    const float* W_x    = (const float*)d_in[4];
    const float* W_dt   = (const float*)d_in[5];
    const float* b_dt   = (const float*)d_in[6];
    const float* A_log  = (const float*)d_in[7];
    const float* D_skip = (const float*)d_in[8];
    const float* W_out  = (const float*)d_in[9];
    float* out = (float*)d_out;

    float *xz, *u, *xdbl, *part, *delta, *y, *qcum, *hend, *hstart, *qct, *Aneg;
    int* flagp;
    cudaGetSymbolAddress((void**)&xz,     g_xz);
    cudaGetSymbolAddress((void**)&u,      g_u);
    cudaGetSymbolAddress((void**)&xdbl,   g_xdbl);
    cudaGetSymbolAddress((void**)&part,   g_part);
    cudaGetSymbolAddress((void**)&delta,  g_delta);
    cudaGetSymbolAddress((void**)&y,      g_y);
    cudaGetSymbolAddress((void**)&qcum,   g_qcum);
    cudaGetSymbolAddress((void**)&hend,   g_hend);
    cudaGetSymbolAddress((void**)&hstart, g_hstart);
    cudaGetSymbolAddress((void**)&qct,    g_qct);
    cudaGetSymbolAddress((void**)&Aneg,   g_Aneg);
    cudaGetSymbolAddress((void**)&flagp,  g_flag);

    __nv_bfloat16 *xh,*xl,*uh,*ul,*xdh,*xdl,*yh,*yl;
    __nv_bfloat16 *winTh,*winTl,*wxTh,*wxTl,*wdtTh,*wdtTl,*woTh,*woTl;
    cudaGetSymbolAddress((void**)&xh,  g_xh);   cudaGetSymbolAddress((void**)&xl,  g_xl);
    cudaGetSymbolAddress((void**)&uh,  g_uh);   cudaGetSymbolAddress((void**)&ul,  g_ul);
    cudaGetSymbolAddress((void**)&xdh, g_xdh);  cudaGetSymbolAddress((void**)&xdl, g_xdl);
    cudaGetSymbolAddress((void**)&yh,  g_yh);   cudaGetSymbolAddress((void**)&yl,  g_yl);
    cudaGetSymbolAddress((void**)&winTh, g_winT_h);  cudaGetSymbolAddress((void**)&winTl, g_winT_l);
    cudaGetSymbolAddress((void**)&wxTh,  g_wxT_h);   cudaGetSymbolAddress((void**)&wxTl,  g_wxT_l);
    cudaGetSymbolAddress((void**)&wdtTh, g_wdtT_h);  cudaGetSymbolAddress((void**)&wdtTl, g_wdtT_l);
    cudaGetSymbolAddress((void**)&woTh,  g_woutT_h); cudaGetSymbolAddress((void**)&woTl,  g_woutT_l);

    static bool attr_set = false;
    if (!attr_set) {
        cudaFuncSetAttribute(gemm_bf16, cudaFuncAttributeMaxDynamicSharedMemorySize,
                             GEMM_SMEM_BYTES);
        attr_set = true;
    }

    dim3 tb(32, 8);

    // launches 1-5 (so that the xz GEMM lands in the ncu -s 5 -c 1 profile slot)
    flag_init_kernel<<<1, 1>>>();
    neg_exp_kernel<<<(DINNER * DSTATE + 255) / 256, 256>>>(A_log, Aneg, DINNER * DSTATE);
    cvt_hl<<<(MTOT * DMODEL / 4 + 255) / 256, 256>>>(x, xh, xl, MTOT * DMODEL / 4);
    tconv<<<dim3(2 * DINNER / 32, DMODEL / 32), tb>>>(W_in, 2 * DINNER, winTh, winTl, DMODEL);
    tconv<<<dim3(XDBL_N / 32, DINNER / 32), tb>>>(W_x, XDBL_N, wxTh, wxTl, DINNER);

    // 1) xz = x @ W_in   [2048 x 4096], K=1024   (launch #6 — profiled)
    gemm_bf16<<<dim3(4096 / 64, MTOT / 128), 256, GEMM_SMEM_BYTES>>>(
        xh, xl, DMODEL, winTh, winTl, DMODEL, nullptr, xz, 2 * DINNER, 0,
        2 * DINNER, DMODEL, 0);

    // 2) conv + silu -> u (+ hi/lo)
    conv_silu_kernel<<<(MTOT * DINNER / 4 + 255) / 256, 256>>>(xz, conv_w, conv_b, u, uh, ul);

    // remaining weight prep
    tconv<<<dim3(DINNER / 32, DTRANK / 32), tb>>>(W_dt, DINNER, wdtTh, wdtTl, DTRANK);
    tconv<<<dim3(DMODEL / 32, DINNER / 32), tb>>>(W_out, DMODEL, woTh, woTl, DINNER);

    // 3) x_dbl = u @ W_x   [2048 x 96], K=2048 via split-K=8 + reduce (+ hi/lo)
    gemm_bf16<<<dim3(2, MTOT / 128, NSPLIT), 256, GEMM_SMEM_BYTES>>>(
        uh, ul, DINNER, wxTh, wxTl, DINNER, nullptr, part, XDBL_N, (size_t)MTOT * XDBL_N,
        XDBL_N, DINNER / NSPLIT, 0);
    reduce_split<<<(MTOT * XDBL_N + 255) / 256, 256>>>(part, xdbl, xdh, xdl, MTOT * XDBL_N);

    // 4) delta = softplus(dt @ W_dt + b_dt)   [2048 x 2048], K=64
    gemm_bf16<<<dim3(DINNER / 64, MTOT / 128), 256, GEMM_SMEM_BYTES>>>(
        xdh, xdl, XDBL_N, wdtTh, wdtTl, DTRANK, b_dt, delta, DINNER, 0,
        DINNER, DTRANK, 1);

    // 5) scan: 3-pass parallel-in-time (fast) + fallback
    scan_pass1<<<dim3(NCH / P1_C, NT), 256>>>(delta, u, xdbl, Aneg, y, qcum,
                                              hend, qct, flagp);
    scan_pass2<<<(DSTATE * NCH + 255) / 256, 256>>>(hend, qct, hstart, flagp);
    scan_pass3<<<(MTOT * DINNER + 255) / 256, 256>>>(y, qcum, hstart, xdbl, u,
                                                     xz, D_skip, yh, yl, flagp);
    scan_fallback<<<(NCH * 8) / 256, 256>>>(delta, u, xdbl, xz, Aneg, D_skip, y, flagp);
    cvt_y_fallback<<<(MTOT * DINNER + 255) / 256, 256>>>(y, yh, yl, flagp);

    // 6) out = y @ W_out   [2048 x 1024], K=2048
    gemm_bf16<<<dim3(DMODEL / 64, MTOT / 128), 256, GEMM_SMEM_BYTES>>>(
        yh, yl, DINNER, woTh, woTl, DINNER, nullptr, out, DMODEL, 0,
        DMODEL, DINNER, 0);
}